// round 11
// baseline (speedup 1.0000x reference)
#include <cuda_runtime.h>
#include <cuda_fp16.h>
#include <cstdint>

#define HW (128*128)

// ---------------- scratch (no allocations allowed) ----------------
__device__ float  g_om[8*27*HW];          // conv1 out: offsets raw, mask = 2*sigmoid
__device__ float  g_xt[8*HW*64];          // x transposed to NHWC [b][pix][c]
__device__ __half g_wdc_h[9*2*2*2048];    // [kf][ch-half][hi/lo][oc64][c32]
__device__ __half g_wom_h[9*2*2*1024];    // [kf][ch-half][hi/lo][oc32][c32]

// ---------------- helpers ----------------
__device__ __forceinline__ uint32_t smem_u32(const void* p){
    uint32_t a;
    asm("{ .reg .u64 t; cvta.to.shared.u64 t, %1; cvt.u32.u64 %0, t; }" : "=r"(a) : "l"(p));
    return a;
}
__device__ __forceinline__ void ldsm_x4(uint32_t &r0,uint32_t &r1,uint32_t &r2,uint32_t &r3, uint32_t addr){
    asm volatile("ldmatrix.sync.aligned.m8n8.x4.shared.b16 {%0,%1,%2,%3}, [%4];"
        : "=r"(r0),"=r"(r1),"=r"(r2),"=r"(r3) : "r"(addr));
}
__device__ __forceinline__ void mma16816(float* d, const uint32_t* a, const uint32_t* b){
    asm volatile("mma.sync.aligned.m16n8k16.row.col.f32.f16.f16.f32 "
        "{%0,%1,%2,%3}, {%4,%5,%6,%7}, {%8,%9}, {%0,%1,%2,%3};"
        : "+f"(d[0]),"+f"(d[1]),"+f"(d[2]),"+f"(d[3])
        : "r"(a[0]),"r"(a[1]),"r"(a[2]),"r"(a[3]), "r"(b[0]),"r"(b[1]));
}
__device__ __forceinline__ uint32_t pack_hi(float a, float b, float &ra, float &rb){
    __half ha = __float2half_rn(a), hb = __float2half_rn(b);
    ra = a - __half2float(ha); rb = b - __half2float(hb);
    __half2 h2 = __halves2half2(ha, hb);
    return *(uint32_t*)&h2;
}
__device__ __forceinline__ uint32_t pack_lo(float ra, float rb){
    __half2 l2 = __floats2half2_rn(ra, rb);
    return *(uint32_t*)&l2;
}
__device__ __forceinline__ void fma4(float4 &acc, float w, float4 p){
    acc.x += w*p.x; acc.y += w*p.y; acc.z += w*p.z; acc.w += w*p.w;
}
__device__ __forceinline__ void cp16(uint32_t dst, const void* src){
    asm volatile("cp.async.cg.shared.global [%0], [%1], 16;" :: "r"(dst), "l"(src));
}
#define CP_COMMIT() asm volatile("cp.async.commit_group;" ::: "memory")
#define CP_WAIT0()  asm volatile("cp.async.wait_group 0;" ::: "memory")

__constant__ int cKY[9] = {-1,-1,-1, 0,0,0, 1,1,1};
__constant__ int cKX[9] = {-1, 0, 1,-1,0,1,-1,0,1};

// ---------------- kernel 0: weight split fp32 -> f16 hi/lo ----------------
__global__ void prep_kernel(const float* __restrict__ w_om, const float* __restrict__ w_dc){
    int i = blockIdx.x * blockDim.x + threadIdx.x;
    if (i < 9*4096){                       // (kf, h, oc64, c32)
        int kf = i >> 12, rem = i & 4095;
        int h = rem >> 11, r2 = rem & 2047;
        float w = w_dc[((r2 >> 5)*64 + h*32 + (r2 & 31))*9 + kf];
        __half hi = __float2half_rn(w);
        __half lo = __float2half_rn(w - __half2float(hi));
        int base = ((kf*2 + h)*2)*2048 + r2;
        g_wdc_h[base]        = hi;
        g_wdc_h[base + 2048] = lo;
    }
    int j = i - 9*4096;
    if (j >= 0 && j < 9*2048){             // (kf, h, oc32, c32)
        int kf = j >> 11, rem = j & 2047;
        int h = rem >> 10, r2 = rem & 1023;
        int oc = r2 >> 5;
        float w = (oc < 27) ? w_om[(oc*64 + h*32 + (r2 & 31))*9 + kf] : 0.f;
        __half hi = __float2half_rn(w);
        __half lo = __float2half_rn(w - __half2float(hi));
        int base = ((kf*2 + h)*2)*1024 + r2;
        g_wom_h[base]        = hi;
        g_wom_h[base + 1024] = lo;
    }
}

// ---------------- kernel 0b: NCHW -> NHWC transpose ----------------
__global__ void __launch_bounds__(256)
transpose_kernel(const float* __restrict__ x){
    __shared__ float tile[64][65];
    const int b   = blockIdx.y;
    const int px0 = blockIdx.x * 64;
    const int t   = threadIdx.x;
    const float* xb = x + (size_t)b*64*HW + px0;
    {
        int cr = t >> 4, pq = t & 15;
        #pragma unroll
        for (int i = 0; i < 4; ++i){
            int c = i*16 + cr;
            float4 v = *(const float4*)(xb + (size_t)c*HW + pq*4);
            tile[c][pq*4+0]=v.x; tile[c][pq*4+1]=v.y;
            tile[c][pq*4+2]=v.z; tile[c][pq*4+3]=v.w;
        }
    }
    __syncthreads();
    {
        int px = t >> 2, cq = t & 3;
        float* ob = g_xt + ((size_t)b*HW + px0 + px)*64 + cq*16;
        #pragma unroll
        for (int i = 0; i < 4; ++i){
            int c = cq*16 + i*4;
            ((float4*)ob)[i] = make_float4(tile[c][px], tile[c+1][px],
                                           tile[c+2][px], tile[c+3][px]);
        }
    }
}

// =====================================================================
// smem: 80B rows (5x16B -> 5r mod 8 distinct banks, conflict-free ldmatrix)
// =====================================================================
#define RST 80

#define CV_XHI  0
#define CV_XLO  10240
#define CV_WHI  20480
#define CV_WLO  23040
#define CV_STG  25600
#define CV_SMEM (2*CV_STG)

#define DF_VHI  0
#define DF_VLO  10240
#define DF_WHI  20480
#define DF_WLO  25600
#define DF_STG  30720
#define DF_SMEM (2*DF_STG)

// B fragment pair loader: x4 gives (b0,b1) for oc-rows [r0,r0+8) and [r0+8,r0+16)
// at k-chunk kc (32B col offset). addr lane map: row = r0 + (L>>4)*8 + (L&7),
// col = kc*32 + ((L>>3)&1)*16.
__device__ __forceinline__ void ldB_pair(uint32_t* b4, uint32_t base, int lane, int r0, int kc){
    uint32_t a = base + (uint32_t)((r0 + ((lane>>4)<<3) + (lane&7))*RST + kc*32 + ((lane>>3)&1)*16);
    ldsm_x4(b4[0], b4[1], b4[2], b4[3], a);
}

// =====================================================================
// kernel 1: 3x3 conv 64->27 (+2*sigmoid), 18 stages of K=32, 4 CTA/SM
// warp = 16px x 32oc
// =====================================================================
__global__ void __launch_bounds__(256, 4)
conv_om_kernel(const float* __restrict__ b_om){
    extern __shared__ char smem[];
    const uint32_t sb = smem_u32(smem);
    const int b   = blockIdx.y;
    const int row = blockIdx.x;
    const int t   = threadIdx.x;
    const int w   = t >> 5, lane = t & 31;
    const int sub = lane >> 3;         // 4 px per warp per p-iter
    const int ch  = (lane & 7) * 4;    // 8 lanes cover 32 ch
    const float* xtb = g_xt + (size_t)b*HW*64;

    float d[4][4];
    #pragma unroll
    for (int i = 0; i < 4; ++i)
        #pragma unroll
        for (int k = 0; k < 4; ++k) d[i][k] = 0.f;

    auto gather = [&](int s, int buf){
        const int kf = s >> 1, h = s & 1;
        char* sg = smem + buf*CV_STG;
        const uint32_t sgu = sb + buf*CV_STG;
        {   // weights: 128 hi + 128 lo 16B-chunks
            int j = t & 127, hl = t >> 7;
            const __half* src = g_wom_h + ((kf*2 + h)*2 + hl)*1024;
            cp16(sgu + (hl ? CV_WLO : CV_WHI) + (j>>2)*RST + (j&3)*16, src + j*8);
        }
        CP_COMMIT();
        const int yy = row + cKY[kf];
        const bool okY = (yy >= 0 && yy < 128);
        #pragma unroll
        for (int p = 0; p < 4; ++p){
            int gpx = p*32 + w*4 + sub;
            int xx = gpx + cKX[kf];
            bool ok = okY && (xx >= 0 && xx < 128);
            float4 v = make_float4(0.f,0.f,0.f,0.f);
            if (ok) v = *(const float4*)(xtb + (size_t)(yy*128 + xx)*64 + h*32 + ch);
            float r0,r1,r2,r3;
            uint32_t h0 = pack_hi(v.x, v.y, r0, r1);
            uint32_t h1 = pack_hi(v.z, v.w, r2, r3);
            *(uint2*)(sg + CV_XHI + gpx*RST + ch*2) = make_uint2(h0, h1);
            *(uint2*)(sg + CV_XLO + gpx*RST + ch*2) = make_uint2(pack_lo(r0,r1), pack_lo(r2,r3));
        }
    };

    gather(0, 0);
    for (int s = 0; s < 18; ++s){
        CP_WAIT0();
        __syncthreads();
        if (s < 17) gather(s + 1, (s + 1) & 1);
        // ---- MMA: A[16px][32c] x B[32oc][32c] ----
        const uint32_t stg = sb + (s & 1)*CV_STG;
        #pragma unroll
        for (int kc = 0; kc < 2; ++kc){
            uint32_t bh01[4], bh23[4], bl01[4], bl23[4];
            ldB_pair(bh01, stg + CV_WHI, lane, 0,  kc);
            ldB_pair(bh23, stg + CV_WHI, lane, 16, kc);
            ldB_pair(bl01, stg + CV_WLO, lane, 0,  kc);
            ldB_pair(bl23, stg + CV_WLO, lane, 16, kc);
            uint32_t ab = stg + (uint32_t)((w*16 + (lane & 15))*RST + ((lane>>4)<<4) + kc*32);
            uint32_t ah[4], al[4];
            ldsm_x4(ah[0],ah[1],ah[2],ah[3], ab + CV_XHI);
            ldsm_x4(al[0],al[1],al[2],al[3], ab + CV_XLO);
            mma16816(d[0], ah, bh01); mma16816(d[0], ah, bl01); mma16816(d[0], al, bh01);
            mma16816(d[1], ah, bh01+2); mma16816(d[1], ah, bl01+2); mma16816(d[1], al, bh01+2);
            mma16816(d[2], ah, bh23); mma16816(d[2], ah, bl23); mma16816(d[2], al, bh23);
            mma16816(d[3], ah, bh23+2); mma16816(d[3], ah, bl23+2); mma16816(d[3], al, bh23+2);
        }
    }

    // epilogue via smem staging: sd[27][132]
    __syncthreads();
    float* sd = (float*)smem;
    const int g  = lane >> 2, t4 = lane & 3;
    #pragma unroll
    for (int nc = 0; nc < 4; ++nc){
        #pragma unroll
        for (int q = 0; q < 4; ++q){
            int oc = 8*nc + 2*t4 + (q & 1);
            if (oc >= 27) continue;
            float v = d[nc][q] + b_om[oc];
            if (oc >= 18) v = 2.f/(1.f + __expf(-v));
            int px = w*16 + g + ((q & 2) ? 8 : 0);
            sd[oc*132 + px] = v;
        }
    }
    __syncthreads();
    if (t < 216){
        int oc = t >> 3, px0 = (t & 7)*16;
        float* dst = g_om + (size_t)b*27*HW + (size_t)oc*HW + row*128 + px0;
        const float* src = sd + oc*132 + px0;
        #pragma unroll
        for (int k = 0; k < 4; ++k)
            ((float4*)dst)[k] = ((const float4*)src)[k];
    }
}

// =====================================================================
// kernel 2: deformable conv 64->64, 18 stages of K=32, 3 CTA/SM
// warp = 32px x 32oc ((4,2) tiling)
// =====================================================================
__global__ void __launch_bounds__(256, 3)
deform_kernel(const float* __restrict__ b_dc, float* __restrict__ out){
    extern __shared__ char smem[];
    const uint32_t sb = smem_u32(smem);
    const int b   = blockIdx.y;
    const int row = blockIdx.x;
    const int t   = threadIdx.x;
    const int w   = t >> 5, lane = t & 31;
    const int pg  = w & 3, og = w >> 2;
    const int sub = lane >> 3;
    const int ch  = (lane & 7) * 4;
    const float* xtb = g_xt + (size_t)b*HW*64;
    const float* omb = g_om + (size_t)b*27*HW;

    // setup-owner: lane sl owns pixel (p = sl>>2, sub' = sl&3)
    const int sl    = lane & 15;
    const int sgpx  = (sl >> 2)*32 + w*4 + (sl & 3);
    const int sgpix = row*128 + sgpx;

    float d[2][4][4];
    #pragma unroll
    for (int i = 0; i < 2; ++i)
        #pragma unroll
        for (int j = 0; j < 4; ++j)
            #pragma unroll
            for (int k = 0; k < 4; ++k) d[i][j][k] = 0.f;

    float sw00, sw01, sw10, sw11;
    int   si00, si01, si10, si11;
    float poy, pox, pom;

    auto load_omb = [&](int kf){
        poy = omb[(size_t)(2*kf    )*HW + sgpix];
        pox = omb[(size_t)(2*kf + 1)*HW + sgpix];
        pom = omb[(size_t)(18 + kf )*HW + sgpix];
    };
    auto comp_setup = [&](int kf){
        float py  = (float)(row  + cKY[kf]) + poy;
        float pxf = (float)(sgpx + cKX[kf]) + pox;
        float y0f = floorf(py), x0f = floorf(pxf);
        float fy = py - y0f, fx = pxf - x0f;
        int y0 = (int)y0f, x0 = (int)x0f, y1 = y0 + 1, x1 = x0 + 1;
        float vy0 = (y0 >= 0 && y0 <= 127) ? 1.f : 0.f;
        float vy1 = (y1 >= 0 && y1 <= 127) ? 1.f : 0.f;
        float vx0 = (x0 >= 0 && x0 <= 127) ? 1.f : 0.f;
        float vx1 = (x1 >= 0 && x1 <= 127) ? 1.f : 0.f;
        sw00 = (1.f-fy)*(1.f-fx)*vy0*vx0*pom;
        sw01 = (1.f-fy)*fx      *vy0*vx1*pom;
        sw10 = fy*(1.f-fx)      *vy1*vx0*pom;
        sw11 = fy*fx            *vy1*vx1*pom;
        int cy0 = min(max(y0,0),127), cy1 = min(max(y1,0),127);
        int cx0 = min(max(x0,0),127), cx1 = min(max(x1,0),127);
        si00 = cy0*128 + cx0; si01 = cy0*128 + cx1;
        si10 = cy1*128 + cx0; si11 = cy1*128 + cx1;
    };
    auto gather = [&](int s, int buf){
        const int kf = s >> 1, h = s & 1;
        char* sg = smem + buf*DF_STG;
        const uint32_t sgu = sb + buf*DF_STG;
        {   // weights: 256 hi + 256 lo chunks, 1 each per thread
            const __half* src = g_wdc_h + ((kf*2 + h)*2)*2048;
            cp16(sgu + DF_WHI + (t>>2)*RST + (t&3)*16, src + t*8);
            cp16(sgu + DF_WLO + (t>>2)*RST + (t&3)*16, src + 2048 + t*8);
        }
        CP_COMMIT();
        #pragma unroll
        for (int p = 0; p < 4; ++p){
            const int src = p*4 + sub;
            float w00 = __shfl_sync(0xffffffffu, sw00, src);
            float w01 = __shfl_sync(0xffffffffu, sw01, src);
            float w10 = __shfl_sync(0xffffffffu, sw10, src);
            float w11 = __shfl_sync(0xffffffffu, sw11, src);
            int   i00 = __shfl_sync(0xffffffffu, si00, src);
            int   i01 = __shfl_sync(0xffffffffu, si01, src);
            int   i10 = __shfl_sync(0xffffffffu, si10, src);
            int   i11 = __shfl_sync(0xffffffffu, si11, src);
            const int gpx = p*32 + w*4 + sub;
            float4 v = make_float4(0.f,0.f,0.f,0.f);
            fma4(v, w00, *(const float4*)(xtb + (size_t)i00*64 + h*32 + ch));
            fma4(v, w01, *(const float4*)(xtb + (size_t)i01*64 + h*32 + ch));
            fma4(v, w10, *(const float4*)(xtb + (size_t)i10*64 + h*32 + ch));
            fma4(v, w11, *(const float4*)(xtb + (size_t)i11*64 + h*32 + ch));
            float r0,r1,r2,r3;
            uint32_t h0 = pack_hi(v.x, v.y, r0, r1);
            uint32_t h1 = pack_hi(v.z, v.w, r2, r3);
            *(uint2*)(sg + DF_VHI + gpx*RST + ch*2) = make_uint2(h0, h1);
            *(uint2*)(sg + DF_VLO + gpx*RST + ch*2) = make_uint2(pack_lo(r0,r1), pack_lo(r2,r3));
        }
    };

    load_omb(0);
    comp_setup(0);
    load_omb(1);
    gather(0, 0);

    for (int s = 0; s < 18; ++s){
        CP_WAIT0();
        __syncthreads();
        if (s < 17){
            if (s & 1) comp_setup((s + 1) >> 1);
            else if (s >= 2 && s <= 14) load_omb((s >> 1) + 1);
            gather(s + 1, (s + 1) & 1);
        }
        // ---- MMA: A[32px][32c] x B[32oc][32c], kc-outer ----
        const uint32_t stg = sb + (s & 1)*DF_STG;
        #pragma unroll
        for (int kc = 0; kc < 2; ++kc){
            uint32_t bh01[4], bh23[4], bl01[4], bl23[4];
            ldB_pair(bh01, stg + DF_WHI, lane, og*32,      kc);
            ldB_pair(bh23, stg + DF_WHI, lane, og*32 + 16, kc);
            ldB_pair(bl01, stg + DF_WLO, lane, og*32,      kc);
            ldB_pair(bl23, stg + DF_WLO, lane, og*32 + 16, kc);
            #pragma unroll
            for (int rbi = 0; rbi < 2; ++rbi){
                uint32_t ab = stg + (uint32_t)((pg*32 + rbi*16 + (lane & 15))*RST
                                               + ((lane>>4)<<4) + kc*32);
                uint32_t ah[4], al[4];
                ldsm_x4(ah[0],ah[1],ah[2],ah[3], ab + DF_VHI);
                ldsm_x4(al[0],al[1],al[2],al[3], ab + DF_VLO);
                mma16816(d[rbi][0], ah, bh01); mma16816(d[rbi][0], ah, bl01); mma16816(d[rbi][0], al, bh01);
                mma16816(d[rbi][1], ah, bh01+2); mma16816(d[rbi][1], ah, bl01+2); mma16816(d[rbi][1], al, bh01+2);
                mma16816(d[rbi][2], ah, bh23); mma16816(d[rbi][2], ah, bl23); mma16816(d[rbi][2], al, bh23);
                mma16816(d[rbi][3], ah, bh23+2); mma16816(d[rbi][3], ah, bl23+2); mma16816(d[rbi][3], al, bh23+2);
            }
        }
    }

    // epilogue via smem staging: sd[64][132]
    __syncthreads();
    float* sd = (float*)smem;
    const int g  = lane >> 2, t4 = lane & 3;
    #pragma unroll
    for (int rbi = 0; rbi < 2; ++rbi){
        #pragma unroll
        for (int nc = 0; nc < 4; ++nc){
            #pragma unroll
            for (int q = 0; q < 4; ++q){
                int oc = og*32 + nc*8 + 2*t4 + (q & 1);
                int px = pg*32 + rbi*16 + g + ((q & 2) ? 8 : 0);
                sd[oc*132 + px] = d[rbi][nc][q] + b_dc[oc];
            }
        }
    }
    __syncthreads();
    {
        int oc = t >> 2, px0 = (t & 3)*32;
        float* dst = out + (size_t)b*64*HW + (size_t)oc*HW + row*128 + px0;
        const float* src = sd + oc*132 + px0;
        #pragma unroll
        for (int k = 0; k < 8; ++k)
            ((float4*)dst)[k] = ((const float4*)src)[k];
    }
}

// ---------------- launch ----------------
extern "C" void kernel_launch(void* const* d_in, const int* in_sizes, int n_in,
                              void* d_out, int out_size){
    const float* x    = (const float*)d_in[0];
    const float* w_om = (const float*)d_in[1];
    const float* b_om = (const float*)d_in[2];
    const float* w_dc = (const float*)d_in[3];
    const float* b_dc = (const float*)d_in[4];
    float* out = (float*)d_out;

    cudaFuncSetAttribute(conv_om_kernel, cudaFuncAttributeMaxDynamicSharedMemorySize, CV_SMEM);
    cudaFuncSetAttribute(deform_kernel,  cudaFuncAttributeMaxDynamicSharedMemorySize, DF_SMEM);

    prep_kernel<<<216, 256>>>(w_om, w_dc);
    transpose_kernel<<<dim3(256, 8), 256>>>(x);
    conv_om_kernel<<<dim3(128, 8), 256, CV_SMEM>>>(b_om);
    deform_kernel <<<dim3(128, 8), 256, DF_SMEM>>>(b_dc, out);
}

// round 12
// speedup vs baseline: 1.3419x; 1.3419x over previous
#include <cuda_runtime.h>
#include <cuda_fp16.h>
#include <cstdint>

#define HW (128*128)

// ---------------- scratch (no allocations allowed) ----------------
__device__ float  g_om[8*27*HW];          // conv1 out: offsets raw, mask = 2*sigmoid
__device__ float  g_xt[8*HW*64];          // x transposed to NHWC [b][pix][c]
__device__ __half g_wdc_h[9*4096];        // [kf][oc(64)][c(64)]  (hi only)
__device__ __half g_wom_h[9*2048];        // [kf][oc(32, 27 used)][c(64)]  (hi only)

// ---------------- helpers ----------------
__device__ __forceinline__ uint32_t smem_u32(const void* p){
    uint32_t a;
    asm("{ .reg .u64 t; cvta.to.shared.u64 t, %1; cvt.u32.u64 %0, t; }" : "=r"(a) : "l"(p));
    return a;
}
__device__ __forceinline__ void ldsm_x4(uint32_t &r0,uint32_t &r1,uint32_t &r2,uint32_t &r3, uint32_t addr){
    asm volatile("ldmatrix.sync.aligned.m8n8.x4.shared.b16 {%0,%1,%2,%3}, [%4];"
        : "=r"(r0),"=r"(r1),"=r"(r2),"=r"(r3) : "r"(addr));
}
__device__ __forceinline__ void mma16816(float* d, const uint32_t* a, const uint32_t* b){
    asm volatile("mma.sync.aligned.m16n8k16.row.col.f32.f16.f16.f32 "
        "{%0,%1,%2,%3}, {%4,%5,%6,%7}, {%8,%9}, {%0,%1,%2,%3};"
        : "+f"(d[0]),"+f"(d[1]),"+f"(d[2]),"+f"(d[3])
        : "r"(a[0]),"r"(a[1]),"r"(a[2]),"r"(a[3]), "r"(b[0]),"r"(b[1]));
}
__device__ __forceinline__ uint32_t pack_hi(float a, float b, float &ra, float &rb){
    __half ha = __float2half_rn(a), hb = __float2half_rn(b);
    ra = a - __half2float(ha); rb = b - __half2float(hb);
    __half2 h2 = __halves2half2(ha, hb);
    return *(uint32_t*)&h2;
}
__device__ __forceinline__ uint32_t pack_lo(float ra, float rb){
    __half2 l2 = __floats2half2_rn(ra, rb);
    return *(uint32_t*)&l2;
}
__device__ __forceinline__ void fma4(float4 &acc, float w, float4 p){
    acc.x += w*p.x; acc.y += w*p.y; acc.z += w*p.z; acc.w += w*p.w;
}

__constant__ int cKY[9] = {-1,-1,-1, 0,0,0, 1,1,1};
__constant__ int cKX[9] = {-1, 0, 1,-1,0,1,-1,0,1};

// ---------------- kernel 0: weight fp32 -> f16 (hi only) ----------------
__global__ void prep_kernel(const float* __restrict__ w_om, const float* __restrict__ w_dc){
    int i = blockIdx.x * blockDim.x + threadIdx.x;
    if (i < 9*4096){
        int kf = i >> 12, rem = i & 4095;
        int oc = rem >> 6, c = rem & 63;
        g_wdc_h[i] = __float2half_rn(w_dc[(oc*64 + c)*9 + kf]);
    }
    int j = i - 9*4096;
    if (j >= 0 && j < 9*2048){
        int kf = j >> 11, rem = j & 2047;
        int oc = rem >> 6, c = rem & 63;
        float w = (oc < 27) ? w_om[(oc*64 + c)*9 + kf] : 0.f;
        g_wom_h[j] = __float2half_rn(w);
    }
}

// ---------------- kernel 0b: NCHW -> NHWC transpose ----------------
__global__ void __launch_bounds__(256)
transpose_kernel(const float* __restrict__ x){
    __shared__ float tile[64][65];
    const int b   = blockIdx.y;
    const int px0 = blockIdx.x * 64;
    const int t   = threadIdx.x;
    const float* xb = x + (size_t)b*64*HW + px0;
    {
        int cr = t >> 4, pq = t & 15;
        #pragma unroll
        for (int i = 0; i < 4; ++i){
            int c = i*16 + cr;
            float4 v = *(const float4*)(xb + (size_t)c*HW + pq*4);
            tile[c][pq*4+0]=v.x; tile[c][pq*4+1]=v.y;
            tile[c][pq*4+2]=v.z; tile[c][pq*4+3]=v.w;
        }
    }
    __syncthreads();
    {
        int px = t >> 2, cq = t & 3;
        float* ob = g_xt + ((size_t)b*HW + px0 + px)*64 + cq*16;
        #pragma unroll
        for (int i = 0; i < 4; ++i){
            int c = cq*16 + i*4;
            ((float4*)ob)[i] = make_float4(tile[c][px], tile[c+1][px],
                                           tile[c+2][px], tile[c+3][px]);
        }
    }
}

// =====================================================================
// smem geometry: rows padded to 72 halves (144 B), conflict-free ldmatrix
// =====================================================================
#define RSTRIDE 144

#define CV_XHI  0
#define CV_XLO  18432
#define CV_WHI  36864
#define CV_STG  41472
#define CV_SMEM (2*CV_STG)

#define DF_VHI  0
#define DF_VLO  18432
#define DF_WHI  36864
#define DF_STG  46080
#define DF_SMEM (2*DF_STG)

// A = values[128px][64c] hi/lo; B = W[n][64c] hi only (2-term emulation)
template<int NC>
__device__ __forceinline__ void mma_tap(uint32_t stg, int vhi_off, int vlo_off,
                                        int whi_off,
                                        int lane, int px0, float d[NC][4]){
    const int arow = px0 + (lane & 15);
    const int akof = (lane >> 4) * 16;
    const uint32_t aBaseHi = stg + vhi_off + arow*RSTRIDE + akof;
    const uint32_t aBaseLo = stg + vlo_off + arow*RSTRIDE + akof;
    uint32_t ah[4][4], al[4][4];
    #pragma unroll
    for (int kc = 0; kc < 4; ++kc){
        ldsm_x4(ah[kc][0],ah[kc][1],ah[kc][2],ah[kc][3], aBaseHi + kc*32);
        ldsm_x4(al[kc][0],al[kc][1],al[kc][2],al[kc][3], aBaseLo + kc*32);
    }
    const uint32_t rb = (lane & 7)*RSTRIDE + ((lane >> 3) & 3)*16;
    #pragma unroll
    for (int nc = 0; nc < NC; ++nc){
        uint32_t bh[4][2];
        const uint32_t bRow = nc*8*RSTRIDE + rb;
        ldsm_x4(bh[0][0],bh[0][1],bh[1][0],bh[1][1], stg + whi_off + bRow);
        ldsm_x4(bh[2][0],bh[2][1],bh[3][0],bh[3][1], stg + whi_off + bRow + 64);
        #pragma unroll
        for (int kc = 0; kc < 4; ++kc){
            mma16816(d[nc], ah[kc], bh[kc]);
            mma16816(d[nc], al[kc], bh[kc]);
        }
    }
}

// =====================================================================
// kernel 1: 3x3 conv 64->27 (+2*sigmoid) via f16x2 mma.sync
// =====================================================================
__global__ void __launch_bounds__(256, 2)
conv_om_kernel(const float* __restrict__ b_om){
    extern __shared__ char smem[];
    const uint32_t sb = smem_u32(smem);
    const int b   = blockIdx.y;
    const int row = blockIdx.x;
    const int t   = threadIdx.x;
    const int w   = t >> 5, lane = t & 31;
    const int sub = lane >> 4;
    const int ch  = (lane & 15) * 4;
    const float* xtb = g_xt + (size_t)b*HW*64;

    float d[4][4];
    #pragma unroll
    for (int i = 0; i < 4; ++i)
        #pragma unroll
        for (int k = 0; k < 4; ++k) d[i][k] = 0.f;

    auto gather = [&](int kf, int buf){
        char* sg = smem + buf*CV_STG;
        {
            const __half* src = g_wom_h + kf*2048;
            int oc = t >> 3, seg = t & 7;
            ((uint4*)(sg + CV_WHI + oc*RSTRIDE + seg*16))[0] = ((const uint4*)src)[t];
        }
        const int yy = row + cKY[kf];
        const bool okY = (yy >= 0 && yy < 128);
        #pragma unroll
        for (int p = 0; p < 8; ++p){
            int gpx = p*16 + w*2 + sub;
            int xx = gpx + cKX[kf];
            bool ok = okY && (xx >= 0 && xx < 128);
            float4 v = make_float4(0.f,0.f,0.f,0.f);
            if (ok) v = *(const float4*)(xtb + (size_t)(yy*128 + xx)*64 + ch);
            float r0,r1,r2,r3;
            uint32_t h0 = pack_hi(v.x, v.y, r0, r1);
            uint32_t h1 = pack_hi(v.z, v.w, r2, r3);
            *(uint2*)(sg + CV_XHI + gpx*RSTRIDE + ch*2) = make_uint2(h0, h1);
            *(uint2*)(sg + CV_XLO + gpx*RSTRIDE + ch*2) = make_uint2(pack_lo(r0,r1), pack_lo(r2,r3));
        }
    };

    gather(0, 0);
    for (int s = 0; s < 9; ++s){
        __syncthreads();
        if (s < 8) gather(s + 1, (s + 1) & 1);
        mma_tap<4>(sb + (s & 1)*CV_STG, CV_XHI, CV_XLO, CV_WHI,
                   lane, w*16, d);
    }

    const int g  = lane >> 2, t4 = lane & 3;
    float* dstb = g_om + (size_t)b*27*HW + row*128;
    #pragma unroll
    for (int nc = 0; nc < 4; ++nc){
        int oc0 = 8*nc + 2*t4;
        #pragma unroll
        for (int q = 0; q < 2; ++q){
            int oc = oc0 + q;
            if (oc >= 27) continue;
            float bv = b_om[oc];
            float v0 = d[nc][q]     + bv;
            float v1 = d[nc][q + 2] + bv;
            if (oc >= 18){
                v0 = 2.f/(1.f + __expf(-v0));
                v1 = 2.f/(1.f + __expf(-v1));
            }
            dstb[(size_t)oc*HW + w*16 + g]     = v0;
            dstb[(size_t)oc*HW + w*16 + g + 8] = v1;
        }
    }
}

// =====================================================================
// kernel 2: deformable conv 64->64 via f16x2 mma.sync
// setup dedup via shfl; offsets pipelined 2 taps ahead (R8 structure)
// =====================================================================
__global__ void __launch_bounds__(256, 2)
deform_kernel(const float* __restrict__ b_dc, float* __restrict__ out){
    extern __shared__ char smem[];
    const uint32_t sb = smem_u32(smem);
    const int b   = blockIdx.y;
    const int row = blockIdx.x;
    const int t   = threadIdx.x;
    const int w   = t >> 5, lane = t & 31;
    const int sub = lane >> 4;
    const int ch  = (lane & 15) * 4;
    const float* xtb = g_xt + (size_t)b*HW*64;
    const float* omb = g_om + (size_t)b*27*HW;

    const int sl    = lane & 15;
    const int sgpx  = (sl & 7)*16 + w*2 + (sl >> 3);
    const int sgpix = row*128 + sgpx;

    float d[8][4];
    #pragma unroll
    for (int i = 0; i < 8; ++i)
        #pragma unroll
        for (int k = 0; k < 4; ++k) d[i][k] = 0.f;

    float sw00, sw01, sw10, sw11;
    int   si00, si01, si10, si11;
    float poy, pox, pom;

    auto load_omb = [&](int kf){
        poy = omb[(size_t)(2*kf    )*HW + sgpix];
        pox = omb[(size_t)(2*kf + 1)*HW + sgpix];
        pom = omb[(size_t)(18 + kf )*HW + sgpix];
    };
    auto comp_setup = [&](int kf){
        float py  = (float)(row  + cKY[kf]) + poy;
        float pxf = (float)(sgpx + cKX[kf]) + pox;
        float y0f = floorf(py), x0f = floorf(pxf);
        float fy = py - y0f, fx = pxf - x0f;
        int y0 = (int)y0f, x0 = (int)x0f, y1 = y0 + 1, x1 = x0 + 1;
        float vy0 = (y0 >= 0 && y0 <= 127) ? 1.f : 0.f;
        float vy1 = (y1 >= 0 && y1 <= 127) ? 1.f : 0.f;
        float vx0 = (x0 >= 0 && x0 <= 127) ? 1.f : 0.f;
        float vx1 = (x1 >= 0 && x1 <= 127) ? 1.f : 0.f;
        sw00 = (1.f-fy)*(1.f-fx)*vy0*vx0*pom;
        sw01 = (1.f-fy)*fx      *vy0*vx1*pom;
        sw10 = fy*(1.f-fx)      *vy1*vx0*pom;
        sw11 = fy*fx            *vy1*vx1*pom;
        int cy0 = min(max(y0,0),127), cy1 = min(max(y1,0),127);
        int cx0 = min(max(x0,0),127), cx1 = min(max(x1,0),127);
        si00 = cy0*128 + cx0; si01 = cy0*128 + cx1;
        si10 = cy1*128 + cx0; si11 = cy1*128 + cx1;
    };
    auto gather = [&](int kf, int buf){
        char* sg = smem + buf*DF_STG;
        {
            const __half* src = g_wdc_h + kf*4096;
            #pragma unroll
            for (int p = 0; p < 2; ++p){
                int j = t + p*256;
                int oc = j >> 3, seg = j & 7;
                ((uint4*)(sg + DF_WHI + oc*RSTRIDE + seg*16))[0] = ((const uint4*)src)[j];
            }
        }
        #pragma unroll
        for (int p = 0; p < 8; ++p){
            const int src = sub*8 + p;
            float w00 = __shfl_sync(0xffffffffu, sw00, src);
            float w01 = __shfl_sync(0xffffffffu, sw01, src);
            float w10 = __shfl_sync(0xffffffffu, sw10, src);
            float w11 = __shfl_sync(0xffffffffu, sw11, src);
            int   i00 = __shfl_sync(0xffffffffu, si00, src);
            int   i01 = __shfl_sync(0xffffffffu, si01, src);
            int   i10 = __shfl_sync(0xffffffffu, si10, src);
            int   i11 = __shfl_sync(0xffffffffu, si11, src);
            const int gpx = p*16 + w*2 + sub;
            float4 v = make_float4(0.f,0.f,0.f,0.f);
            fma4(v, w00, *(const float4*)(xtb + (size_t)i00*64 + ch));
            fma4(v, w01, *(const float4*)(xtb + (size_t)i01*64 + ch));
            fma4(v, w10, *(const float4*)(xtb + (size_t)i10*64 + ch));
            fma4(v, w11, *(const float4*)(xtb + (size_t)i11*64 + ch));
            float r0,r1,r2,r3;
            uint32_t h0 = pack_hi(v.x, v.y, r0, r1);
            uint32_t h1 = pack_hi(v.z, v.w, r2, r3);
            *(uint2*)(sg + DF_VHI + gpx*RSTRIDE + ch*2) = make_uint2(h0, h1);
            *(uint2*)(sg + DF_VLO + gpx*RSTRIDE + ch*2) = make_uint2(pack_lo(r0,r1), pack_lo(r2,r3));
        }
    };

    load_omb(0);
    comp_setup(0);
    load_omb(1);
    gather(0, 0);

    for (int s = 0; s < 9; ++s){
        __syncthreads();
        if (s < 8){
            comp_setup(s + 1);
            if (s < 7) load_omb(s + 2);
            gather(s + 1, (s + 1) & 1);
        }
        mma_tap<8>(sb + (s & 1)*DF_STG, DF_VHI, DF_VLO, DF_WHI,
                   lane, w*16, d);
    }

    const int g  = lane >> 2, t4 = lane & 3;
    float* dstb = out + (size_t)b*64*HW + row*128;
    #pragma unroll
    for (int nc = 0; nc < 8; ++nc){
        int oc0 = 8*nc + 2*t4;
        #pragma unroll
        for (int q = 0; q < 2; ++q){
            int oc = oc0 + q;
            float bv = b_dc[oc];
            dstb[(size_t)oc*HW + w*16 + g]     = d[nc][q]     + bv;
            dstb[(size_t)oc*HW + w*16 + g + 8] = d[nc][q + 2] + bv;
        }
    }
}

// ---------------- launch ----------------
extern "C" void kernel_launch(void* const* d_in, const int* in_sizes, int n_in,
                              void* d_out, int out_size){
    const float* x    = (const float*)d_in[0];
    const float* w_om = (const float*)d_in[1];
    const float* b_om = (const float*)d_in[2];
    const float* w_dc = (const float*)d_in[3];
    const float* b_dc = (const float*)d_in[4];
    float* out = (float*)d_out;

    cudaFuncSetAttribute(conv_om_kernel, cudaFuncAttributeMaxDynamicSharedMemorySize, CV_SMEM);
    cudaFuncSetAttribute(deform_kernel,  cudaFuncAttributeMaxDynamicSharedMemorySize, DF_SMEM);

    prep_kernel<<<216, 256>>>(w_om, w_dc);
    transpose_kernel<<<dim3(256, 8), 256>>>(x);
    conv_om_kernel<<<dim3(128, 8), 256, CV_SMEM>>>(b_om);
    deform_kernel <<<dim3(128, 8), 256, DF_SMEM>>>(b_dc, out);
}

// round 13
// speedup vs baseline: 1.5496x; 1.1548x over previous
#include <cuda_runtime.h>
#include <cuda_fp16.h>
#include <cstdint>

#define HW (128*128)

// ---------------- scratch (no allocations allowed) ----------------
__device__ float  g_om[8*27*HW];          // conv1 out: offsets raw, mask = 2*sigmoid
__device__ float  g_xt[8*HW*64];          // x transposed to NHWC [b][pix][c]
__device__ __half g_wdc_h[9*4096];        // [kf][oc(64)][c(64)]  (f16)
__device__ __half g_wom_h[9*2048];        // [kf][oc(32, 27 used)][c(64)]  (f16)

// ---------------- helpers ----------------
__device__ __forceinline__ uint32_t smem_u32(const void* p){
    uint32_t a;
    asm("{ .reg .u64 t; cvta.to.shared.u64 t, %1; cvt.u32.u64 %0, t; }" : "=r"(a) : "l"(p));
    return a;
}
__device__ __forceinline__ void ldsm_x4(uint32_t &r0,uint32_t &r1,uint32_t &r2,uint32_t &r3, uint32_t addr){
    asm volatile("ldmatrix.sync.aligned.m8n8.x4.shared.b16 {%0,%1,%2,%3}, [%4];"
        : "=r"(r0),"=r"(r1),"=r"(r2),"=r"(r3) : "r"(addr));
}
__device__ __forceinline__ void mma16816(float* d, const uint32_t* a, const uint32_t* b){
    asm volatile("mma.sync.aligned.m16n8k16.row.col.f32.f16.f16.f32 "
        "{%0,%1,%2,%3}, {%4,%5,%6,%7}, {%8,%9}, {%0,%1,%2,%3};"
        : "+f"(d[0]),"+f"(d[1]),"+f"(d[2]),"+f"(d[3])
        : "r"(a[0]),"r"(a[1]),"r"(a[2]),"r"(a[3]), "r"(b[0]),"r"(b[1]));
}
__device__ __forceinline__ uint32_t pack2h(float a, float b){
    __half2 h2 = __floats2half2_rn(a, b);
    return *(uint32_t*)&h2;
}
__device__ __forceinline__ void fma4(float4 &acc, float w, float4 p){
    acc.x += w*p.x; acc.y += w*p.y; acc.z += w*p.z; acc.w += w*p.w;
}

__constant__ int cKY[9] = {-1,-1,-1, 0,0,0, 1,1,1};
__constant__ int cKX[9] = {-1, 0, 1,-1,0,1,-1,0,1};

// ---------------- kernel 0: weight fp32 -> f16 ----------------
__global__ void prep_kernel(const float* __restrict__ w_om, const float* __restrict__ w_dc){
    int i = blockIdx.x * blockDim.x + threadIdx.x;
    if (i < 9*4096){
        int kf = i >> 12, rem = i & 4095;
        int oc = rem >> 6, c = rem & 63;
        g_wdc_h[i] = __float2half_rn(w_dc[(oc*64 + c)*9 + kf]);
    }
    int j = i - 9*4096;
    if (j >= 0 && j < 9*2048){
        int kf = j >> 11, rem = j & 2047;
        int oc = rem >> 6, c = rem & 63;
        float w = (oc < 27) ? w_om[(oc*64 + c)*9 + kf] : 0.f;
        g_wom_h[j] = __float2half_rn(w);
    }
}

// ---------------- kernel 0b: NCHW -> NHWC transpose ----------------
__global__ void __launch_bounds__(256)
transpose_kernel(const float* __restrict__ x){
    __shared__ float tile[64][65];
    const int b   = blockIdx.y;
    const int px0 = blockIdx.x * 64;
    const int t   = threadIdx.x;
    const float* xb = x + (size_t)b*64*HW + px0;
    {
        int cr = t >> 4, pq = t & 15;
        #pragma unroll
        for (int i = 0; i < 4; ++i){
            int c = i*16 + cr;
            float4 v = *(const float4*)(xb + (size_t)c*HW + pq*4);
            tile[c][pq*4+0]=v.x; tile[c][pq*4+1]=v.y;
            tile[c][pq*4+2]=v.z; tile[c][pq*4+3]=v.w;
        }
    }
    __syncthreads();
    {
        int px = t >> 2, cq = t & 3;
        float* ob = g_xt + ((size_t)b*HW + px0 + px)*64 + cq*16;
        #pragma unroll
        for (int i = 0; i < 4; ++i){
            int c = cq*16 + i*4;
            ((float4*)ob)[i] = make_float4(tile[c][px], tile[c+1][px],
                                           tile[c+2][px], tile[c+3][px]);
        }
    }
}

// =====================================================================
// smem geometry: rows padded to 72 halves (144 B), conflict-free ldmatrix
// =====================================================================
#define RSTRIDE 144

#define CV_XHI  0
#define CV_WHI  18432
#define CV_STG  23040
#define CV_SMEM (2*CV_STG)

#define DF_VHI  0
#define DF_WHI  18432
#define DF_STG  27648
#define DF_SMEM (2*DF_STG)

// A = values[128px][64c] f16, B = W[n][64c] f16 (plain f16 MMA)
template<int NC>
__device__ __forceinline__ void mma_tap(uint32_t stg, int vhi_off, int whi_off,
                                        int lane, int px0, float d[NC][4]){
    const int arow = px0 + (lane & 15);
    const int akof = (lane >> 4) * 16;
    const uint32_t aBase = stg + vhi_off + arow*RSTRIDE + akof;
    uint32_t ah[4][4];
    #pragma unroll
    for (int kc = 0; kc < 4; ++kc)
        ldsm_x4(ah[kc][0],ah[kc][1],ah[kc][2],ah[kc][3], aBase + kc*32);
    const uint32_t rb = (lane & 7)*RSTRIDE + ((lane >> 3) & 3)*16;
    #pragma unroll
    for (int nc = 0; nc < NC; ++nc){
        uint32_t bh[4][2];
        const uint32_t bRow = nc*8*RSTRIDE + rb;
        ldsm_x4(bh[0][0],bh[0][1],bh[1][0],bh[1][1], stg + whi_off + bRow);
        ldsm_x4(bh[2][0],bh[2][1],bh[3][0],bh[3][1], stg + whi_off + bRow + 64);
        #pragma unroll
        for (int kc = 0; kc < 4; ++kc)
            mma16816(d[nc], ah[kc], bh[kc]);
    }
}

// =====================================================================
// kernel 1: 3x3 conv 64->27 (+2*sigmoid) via f16 mma.sync
// =====================================================================
__global__ void __launch_bounds__(256, 2)
conv_om_kernel(const float* __restrict__ b_om){
    extern __shared__ char smem[];
    const uint32_t sb = smem_u32(smem);
    const int b   = blockIdx.y;
    const int row = blockIdx.x;
    const int t   = threadIdx.x;
    const int w   = t >> 5, lane = t & 31;
    const int sub = lane >> 4;
    const int ch  = (lane & 15) * 4;
    const float* xtb = g_xt + (size_t)b*HW*64;

    float d[4][4];
    #pragma unroll
    for (int i = 0; i < 4; ++i)
        #pragma unroll
        for (int k = 0; k < 4; ++k) d[i][k] = 0.f;

    auto gather = [&](int kf, int buf){
        char* sg = smem + buf*CV_STG;
        {
            const __half* src = g_wom_h + kf*2048;
            int oc = t >> 3, seg = t & 7;
            ((uint4*)(sg + CV_WHI + oc*RSTRIDE + seg*16))[0] = ((const uint4*)src)[t];
        }
        const int yy = row + cKY[kf];
        const bool okY = (yy >= 0 && yy < 128);
        #pragma unroll
        for (int p = 0; p < 8; ++p){
            int gpx = p*16 + w*2 + sub;
            int xx = gpx + cKX[kf];
            bool ok = okY && (xx >= 0 && xx < 128);
            float4 v = make_float4(0.f,0.f,0.f,0.f);
            if (ok) v = *(const float4*)(xtb + (size_t)(yy*128 + xx)*64 + ch);
            *(uint2*)(sg + CV_XHI + gpx*RSTRIDE + ch*2) =
                make_uint2(pack2h(v.x, v.y), pack2h(v.z, v.w));
        }
    };

    gather(0, 0);
    for (int s = 0; s < 9; ++s){
        __syncthreads();
        if (s < 8) gather(s + 1, (s + 1) & 1);
        mma_tap<4>(sb + (s & 1)*CV_STG, CV_XHI, CV_WHI, lane, w*16, d);
    }

    const int g  = lane >> 2, t4 = lane & 3;
    float* dstb = g_om + (size_t)b*27*HW + row*128;
    #pragma unroll
    for (int nc = 0; nc < 4; ++nc){
        int oc0 = 8*nc + 2*t4;
        #pragma unroll
        for (int q = 0; q < 2; ++q){
            int oc = oc0 + q;
            if (oc >= 27) continue;
            float bv = b_om[oc];
            float v0 = d[nc][q]     + bv;
            float v1 = d[nc][q + 2] + bv;
            if (oc >= 18){
                v0 = 2.f/(1.f + __expf(-v0));
                v1 = 2.f/(1.f + __expf(-v1));
            }
            dstb[(size_t)oc*HW + w*16 + g]     = v0;
            dstb[(size_t)oc*HW + w*16 + g + 8] = v1;
        }
    }
}

// =====================================================================
// kernel 2: deformable conv 64->64 via f16 mma.sync
// setup dedup via shfl; offsets pipelined 2 taps ahead (R8/R12 structure)
// =====================================================================
__global__ void __launch_bounds__(256, 2)
deform_kernel(const float* __restrict__ b_dc, float* __restrict__ out){
    extern __shared__ char smem[];
    const uint32_t sb = smem_u32(smem);
    const int b   = blockIdx.y;
    const int row = blockIdx.x;
    const int t   = threadIdx.x;
    const int w   = t >> 5, lane = t & 31;
    const int sub = lane >> 4;
    const int ch  = (lane & 15) * 4;
    const float* xtb = g_xt + (size_t)b*HW*64;
    const float* omb = g_om + (size_t)b*27*HW;

    const int sl    = lane & 15;
    const int sgpx  = (sl & 7)*16 + w*2 + (sl >> 3);
    const int sgpix = row*128 + sgpx;

    float d[8][4];
    #pragma unroll
    for (int i = 0; i < 8; ++i)
        #pragma unroll
        for (int k = 0; k < 4; ++k) d[i][k] = 0.f;

    float sw00, sw01, sw10, sw11;
    int   si00, si01, si10, si11;
    float poy, pox, pom;

    auto load_omb = [&](int kf){
        poy = omb[(size_t)(2*kf    )*HW + sgpix];
        pox = omb[(size_t)(2*kf + 1)*HW + sgpix];
        pom = omb[(size_t)(18 + kf )*HW + sgpix];
    };
    auto comp_setup = [&](int kf){
        float py  = (float)(row  + cKY[kf]) + poy;
        float pxf = (float)(sgpx + cKX[kf]) + pox;
        float y0f = floorf(py), x0f = floorf(pxf);
        float fy = py - y0f, fx = pxf - x0f;
        int y0 = (int)y0f, x0 = (int)x0f, y1 = y0 + 1, x1 = x0 + 1;
        float vy0 = (y0 >= 0 && y0 <= 127) ? 1.f : 0.f;
        float vy1 = (y1 >= 0 && y1 <= 127) ? 1.f : 0.f;
        float vx0 = (x0 >= 0 && x0 <= 127) ? 1.f : 0.f;
        float vx1 = (x1 >= 0 && x1 <= 127) ? 1.f : 0.f;
        sw00 = (1.f-fy)*(1.f-fx)*vy0*vx0*pom;
        sw01 = (1.f-fy)*fx      *vy0*vx1*pom;
        sw10 = fy*(1.f-fx)      *vy1*vx0*pom;
        sw11 = fy*fx            *vy1*vx1*pom;
        int cy0 = min(max(y0,0),127), cy1 = min(max(y1,0),127);
        int cx0 = min(max(x0,0),127), cx1 = min(max(x1,0),127);
        si00 = cy0*128 + cx0; si01 = cy0*128 + cx1;
        si10 = cy1*128 + cx0; si11 = cy1*128 + cx1;
    };
    auto gather = [&](int kf, int buf){
        char* sg = smem + buf*DF_STG;
        {
            const __half* src = g_wdc_h + kf*4096;
            #pragma unroll
            for (int p = 0; p < 2; ++p){
                int j = t + p*256;
                int oc = j >> 3, seg = j & 7;
                ((uint4*)(sg + DF_WHI + oc*RSTRIDE + seg*16))[0] = ((const uint4*)src)[j];
            }
        }
        #pragma unroll
        for (int p = 0; p < 8; ++p){
            const int src = sub*8 + p;
            float w00 = __shfl_sync(0xffffffffu, sw00, src);
            float w01 = __shfl_sync(0xffffffffu, sw01, src);
            float w10 = __shfl_sync(0xffffffffu, sw10, src);
            float w11 = __shfl_sync(0xffffffffu, sw11, src);
            int   i00 = __shfl_sync(0xffffffffu, si00, src);
            int   i01 = __shfl_sync(0xffffffffu, si01, src);
            int   i10 = __shfl_sync(0xffffffffu, si10, src);
            int   i11 = __shfl_sync(0xffffffffu, si11, src);
            const int gpx = p*16 + w*2 + sub;
            float4 v = make_float4(0.f,0.f,0.f,0.f);
            fma4(v, w00, *(const float4*)(xtb + (size_t)i00*64 + ch));
            fma4(v, w01, *(const float4*)(xtb + (size_t)i01*64 + ch));
            fma4(v, w10, *(const float4*)(xtb + (size_t)i10*64 + ch));
            fma4(v, w11, *(const float4*)(xtb + (size_t)i11*64 + ch));
            *(uint2*)(sg + DF_VHI + gpx*RSTRIDE + ch*2) =
                make_uint2(pack2h(v.x, v.y), pack2h(v.z, v.w));
        }
    };

    load_omb(0);
    comp_setup(0);
    load_omb(1);
    gather(0, 0);

    for (int s = 0; s < 9; ++s){
        __syncthreads();
        if (s < 8){
            comp_setup(s + 1);
            if (s < 7) load_omb(s + 2);
            gather(s + 1, (s + 1) & 1);
        }
        mma_tap<8>(sb + (s & 1)*DF_STG, DF_VHI, DF_WHI, lane, w*16, d);
    }

    const int g  = lane >> 2, t4 = lane & 3;
    float* dstb = out + (size_t)b*64*HW + row*128;
    #pragma unroll
    for (int nc = 0; nc < 8; ++nc){
        int oc0 = 8*nc + 2*t4;
        #pragma unroll
        for (int q = 0; q < 2; ++q){
            int oc = oc0 + q;
            float bv = b_dc[oc];
            dstb[(size_t)oc*HW + w*16 + g]     = d[nc][q]     + bv;
            dstb[(size_t)oc*HW + w*16 + g + 8] = d[nc][q + 2] + bv;
        }
    }
}

// ---------------- launch ----------------
extern "C" void kernel_launch(void* const* d_in, const int* in_sizes, int n_in,
                              void* d_out, int out_size){
    const float* x    = (const float*)d_in[0];
    const float* w_om = (const float*)d_in[1];
    const float* b_om = (const float*)d_in[2];
    const float* w_dc = (const float*)d_in[3];
    const float* b_dc = (const float*)d_in[4];
    float* out = (float*)d_out;

    cudaFuncSetAttribute(conv_om_kernel, cudaFuncAttributeMaxDynamicSharedMemorySize, CV_SMEM);
    cudaFuncSetAttribute(deform_kernel,  cudaFuncAttributeMaxDynamicSharedMemorySize, DF_SMEM);

    prep_kernel<<<216, 256>>>(w_om, w_dc);
    transpose_kernel<<<dim3(256, 8), 256>>>(x);
    conv_om_kernel<<<dim3(128, 8), 256, CV_SMEM>>>(b_om);
    deform_kernel <<<dim3(128, 8), 256, DF_SMEM>>>(b_dc, out);
}

// round 14
// speedup vs baseline: 1.8580x; 1.1990x over previous
#include <cuda_runtime.h>
#include <cuda_fp16.h>
#include <cstdint>

#define HW (128*128)

// ---------------- scratch (no allocations allowed) ----------------
__device__ float  g_om[8*27*HW];          // conv1 out: offsets raw, mask = 2*sigmoid
__device__ __half g_xt[8*HW*64];          // x transposed to NHWC f16 [b][pix][c]
__device__ __half g_wdc_h[9*4096];        // [kf][oc(64)][c(64)]  (f16)
__device__ __half g_wom_h[9*2048];        // [kf][oc(32, 27 used)][c(64)]  (f16)

// ---------------- helpers ----------------
__device__ __forceinline__ uint32_t smem_u32(const void* p){
    uint32_t a;
    asm("{ .reg .u64 t; cvta.to.shared.u64 t, %1; cvt.u32.u64 %0, t; }" : "=r"(a) : "l"(p));
    return a;
}
__device__ __forceinline__ void ldsm_x4(uint32_t &r0,uint32_t &r1,uint32_t &r2,uint32_t &r3, uint32_t addr){
    asm volatile("ldmatrix.sync.aligned.m8n8.x4.shared.b16 {%0,%1,%2,%3}, [%4];"
        : "=r"(r0),"=r"(r1),"=r"(r2),"=r"(r3) : "r"(addr));
}
__device__ __forceinline__ void mma16816(float* d, const uint32_t* a, const uint32_t* b){
    asm volatile("mma.sync.aligned.m16n8k16.row.col.f32.f16.f16.f32 "
        "{%0,%1,%2,%3}, {%4,%5,%6,%7}, {%8,%9}, {%0,%1,%2,%3};"
        : "+f"(d[0]),"+f"(d[1]),"+f"(d[2]),"+f"(d[3])
        : "r"(a[0]),"r"(a[1]),"r"(a[2]),"r"(a[3]), "r"(b[0]),"r"(b[1]));
}
__device__ __forceinline__ uint32_t pack2h(float a, float b){
    __half2 h2 = __floats2half2_rn(a, b);
    return *(uint32_t*)&h2;
}
__device__ __forceinline__ float4 h4_to_f4(uint2 r){
    __half2* h = (__half2*)&r;
    float2 a = __half22float2(h[0]);
    float2 b = __half22float2(h[1]);
    return make_float4(a.x, a.y, b.x, b.y);
}
__device__ __forceinline__ void fma4(float4 &acc, float w, float4 p){
    acc.x += w*p.x; acc.y += w*p.y; acc.z += w*p.z; acc.w += w*p.w;
}

__constant__ int cKY[9] = {-1,-1,-1, 0,0,0, 1,1,1};
__constant__ int cKX[9] = {-1, 0, 1,-1,0,1,-1,0,1};

// ---------------- kernel 0: weight fp32 -> f16 ----------------
__global__ void prep_kernel(const float* __restrict__ w_om, const float* __restrict__ w_dc){
    int i = blockIdx.x * blockDim.x + threadIdx.x;
    if (i < 9*4096){
        int kf = i >> 12, rem = i & 4095;
        int oc = rem >> 6, c = rem & 63;
        g_wdc_h[i] = __float2half_rn(w_dc[(oc*64 + c)*9 + kf]);
    }
    int j = i - 9*4096;
    if (j >= 0 && j < 9*2048){
        int kf = j >> 11, rem = j & 2047;
        int oc = rem >> 6, c = rem & 63;
        float w = (oc < 27) ? w_om[(oc*64 + c)*9 + kf] : 0.f;
        g_wom_h[j] = __float2half_rn(w);
    }
}

// ---------------- kernel 0b: NCHW fp32 -> NHWC f16 transpose ----------------
__global__ void __launch_bounds__(256)
transpose_kernel(const float* __restrict__ x){
    __shared__ float tile[64][65];
    const int b   = blockIdx.y;
    const int px0 = blockIdx.x * 64;
    const int t   = threadIdx.x;
    const float* xb = x + (size_t)b*64*HW + px0;
    {
        int cr = t >> 4, pq = t & 15;
        #pragma unroll
        for (int i = 0; i < 4; ++i){
            int c = i*16 + cr;
            float4 v = *(const float4*)(xb + (size_t)c*HW + pq*4);
            tile[c][pq*4+0]=v.x; tile[c][pq*4+1]=v.y;
            tile[c][pq*4+2]=v.z; tile[c][pq*4+3]=v.w;
        }
    }
    __syncthreads();
    {
        int px = t >> 2, cq = t & 3;
        __half* ob = g_xt + ((size_t)b*HW + px0 + px)*64 + cq*16;
        #pragma unroll
        for (int i = 0; i < 2; ++i){
            int c = cq*16 + i*8;
            uint4 u;
            u.x = pack2h(tile[c+0][px], tile[c+1][px]);
            u.y = pack2h(tile[c+2][px], tile[c+3][px]);
            u.z = pack2h(tile[c+4][px], tile[c+5][px]);
            u.w = pack2h(tile[c+6][px], tile[c+7][px]);
            ((uint4*)ob)[i] = u;
        }
    }
}

// =====================================================================
// smem geometry: rows padded to 72 halves (144 B), conflict-free ldmatrix
// =====================================================================
#define RSTRIDE 144

#define CV_XHI  0
#define CV_WHI  18432
#define CV_STG  23040
#define CV_SMEM (2*CV_STG)

#define DF_VHI  0
#define DF_WHI  18432
#define DF_STG  27648
#define DF_SMEM (2*DF_STG)

// A = values[128px][64c] f16, B = W[n][64c] f16 (plain f16 MMA)
template<int NC>
__device__ __forceinline__ void mma_tap(uint32_t stg, int vhi_off, int whi_off,
                                        int lane, int px0, float d[NC][4]){
    const int arow = px0 + (lane & 15);
    const int akof = (lane >> 4) * 16;
    const uint32_t aBase = stg + vhi_off + arow*RSTRIDE + akof;
    uint32_t ah[4][4];
    #pragma unroll
    for (int kc = 0; kc < 4; ++kc)
        ldsm_x4(ah[kc][0],ah[kc][1],ah[kc][2],ah[kc][3], aBase + kc*32);
    const uint32_t rb = (lane & 7)*RSTRIDE + ((lane >> 3) & 3)*16;
    #pragma unroll
    for (int nc = 0; nc < NC; ++nc){
        uint32_t bh[4][2];
        const uint32_t bRow = nc*8*RSTRIDE + rb;
        ldsm_x4(bh[0][0],bh[0][1],bh[1][0],bh[1][1], stg + whi_off + bRow);
        ldsm_x4(bh[2][0],bh[2][1],bh[3][0],bh[3][1], stg + whi_off + bRow + 64);
        #pragma unroll
        for (int kc = 0; kc < 4; ++kc)
            mma16816(d[nc], ah[kc], bh[kc]);
    }
}

// =====================================================================
// kernel 1: 3x3 conv 64->27 (+2*sigmoid) via f16 mma.sync
// gather: f16 source, verbatim uint2 copy into smem
// =====================================================================
__global__ void __launch_bounds__(256, 2)
conv_om_kernel(const float* __restrict__ b_om){
    extern __shared__ char smem[];
    const uint32_t sb = smem_u32(smem);
    const int b   = blockIdx.y;
    const int row = blockIdx.x;
    const int t   = threadIdx.x;
    const int w   = t >> 5, lane = t & 31;
    const int sub = lane >> 4;
    const int ch  = (lane & 15) * 4;
    const __half* xtb = g_xt + (size_t)b*HW*64;

    float d[4][4];
    #pragma unroll
    for (int i = 0; i < 4; ++i)
        #pragma unroll
        for (int k = 0; k < 4; ++k) d[i][k] = 0.f;

    auto gather = [&](int kf, int buf){
        char* sg = smem + buf*CV_STG;
        {
            const __half* src = g_wom_h + kf*2048;
            int oc = t >> 3, seg = t & 7;
            ((uint4*)(sg + CV_WHI + oc*RSTRIDE + seg*16))[0] = ((const uint4*)src)[t];
        }
        const int yy = row + cKY[kf];
        const bool okY = (yy >= 0 && yy < 128);
        #pragma unroll
        for (int p = 0; p < 8; ++p){
            int gpx = p*16 + w*2 + sub;
            int xx = gpx + cKX[kf];
            bool ok = okY && (xx >= 0 && xx < 128);
            uint2 v = make_uint2(0u, 0u);
            if (ok) v = *(const uint2*)(xtb + (size_t)(yy*128 + xx)*64 + ch);
            *(uint2*)(sg + CV_XHI + gpx*RSTRIDE + ch*2) = v;
        }
    };

    gather(0, 0);
    for (int s = 0; s < 9; ++s){
        __syncthreads();
        if (s < 8) gather(s + 1, (s + 1) & 1);
        mma_tap<4>(sb + (s & 1)*CV_STG, CV_XHI, CV_WHI, lane, w*16, d);
    }

    const int g  = lane >> 2, t4 = lane & 3;
    float* dstb = g_om + (size_t)b*27*HW + row*128;
    #pragma unroll
    for (int nc = 0; nc < 4; ++nc){
        int oc0 = 8*nc + 2*t4;
        #pragma unroll
        for (int q = 0; q < 2; ++q){
            int oc = oc0 + q;
            if (oc >= 27) continue;
            float bv = b_om[oc];
            float v0 = d[nc][q]     + bv;
            float v1 = d[nc][q + 2] + bv;
            if (oc >= 18){
                v0 = 2.f/(1.f + __expf(-v0));
                v1 = 2.f/(1.f + __expf(-v1));
            }
            dstb[(size_t)oc*HW + w*16 + g]     = v0;
            dstb[(size_t)oc*HW + w*16 + g + 8] = v1;
        }
    }
}

// =====================================================================
// kernel 2: deformable conv 64->64 via f16 mma.sync
// f16 corner loads (uint2), f32 bilinear, f16 pack; R8/R12 structure
// =====================================================================
__global__ void __launch_bounds__(256, 2)
deform_kernel(const float* __restrict__ b_dc, float* __restrict__ out){
    extern __shared__ char smem[];
    const uint32_t sb = smem_u32(smem);
    const int b   = blockIdx.y;
    const int row = blockIdx.x;
    const int t   = threadIdx.x;
    const int w   = t >> 5, lane = t & 31;
    const int sub = lane >> 4;
    const int ch  = (lane & 15) * 4;
    const __half* xtb = g_xt + (size_t)b*HW*64;
    const float*  omb = g_om + (size_t)b*27*HW;

    const int sl    = lane & 15;
    const int sgpx  = (sl & 7)*16 + w*2 + (sl >> 3);
    const int sgpix = row*128 + sgpx;

    float d[8][4];
    #pragma unroll
    for (int i = 0; i < 8; ++i)
        #pragma unroll
        for (int k = 0; k < 4; ++k) d[i][k] = 0.f;

    float sw00, sw01, sw10, sw11;
    int   si00, si01, si10, si11;
    float poy, pox, pom;

    auto load_omb = [&](int kf){
        poy = omb[(size_t)(2*kf    )*HW + sgpix];
        pox = omb[(size_t)(2*kf + 1)*HW + sgpix];
        pom = omb[(size_t)(18 + kf )*HW + sgpix];
    };
    auto comp_setup = [&](int kf){
        float py  = (float)(row  + cKY[kf]) + poy;
        float pxf = (float)(sgpx + cKX[kf]) + pox;
        float y0f = floorf(py), x0f = floorf(pxf);
        float fy = py - y0f, fx = pxf - x0f;
        int y0 = (int)y0f, x0 = (int)x0f, y1 = y0 + 1, x1 = x0 + 1;
        float vy0 = (y0 >= 0 && y0 <= 127) ? 1.f : 0.f;
        float vy1 = (y1 >= 0 && y1 <= 127) ? 1.f : 0.f;
        float vx0 = (x0 >= 0 && x0 <= 127) ? 1.f : 0.f;
        float vx1 = (x1 >= 0 && x1 <= 127) ? 1.f : 0.f;
        sw00 = (1.f-fy)*(1.f-fx)*vy0*vx0*pom;
        sw01 = (1.f-fy)*fx      *vy0*vx1*pom;
        sw10 = fy*(1.f-fx)      *vy1*vx0*pom;
        sw11 = fy*fx            *vy1*vx1*pom;
        int cy0 = min(max(y0,0),127), cy1 = min(max(y1,0),127);
        int cx0 = min(max(x0,0),127), cx1 = min(max(x1,0),127);
        si00 = cy0*128 + cx0; si01 = cy0*128 + cx1;
        si10 = cy1*128 + cx0; si11 = cy1*128 + cx1;
    };
    auto gather = [&](int kf, int buf){
        char* sg = smem + buf*DF_STG;
        {
            const __half* src = g_wdc_h + kf*4096;
            #pragma unroll
            for (int p = 0; p < 2; ++p){
                int j = t + p*256;
                int oc = j >> 3, seg = j & 7;
                ((uint4*)(sg + DF_WHI + oc*RSTRIDE + seg*16))[0] = ((const uint4*)src)[j];
            }
        }
        #pragma unroll
        for (int p = 0; p < 8; ++p){
            const int src = sub*8 + p;
            float w00 = __shfl_sync(0xffffffffu, sw00, src);
            float w01 = __shfl_sync(0xffffffffu, sw01, src);
            float w10 = __shfl_sync(0xffffffffu, sw10, src);
            float w11 = __shfl_sync(0xffffffffu, sw11, src);
            int   i00 = __shfl_sync(0xffffffffu, si00, src);
            int   i01 = __shfl_sync(0xffffffffu, si01, src);
            int   i10 = __shfl_sync(0xffffffffu, si10, src);
            int   i11 = __shfl_sync(0xffffffffu, si11, src);
            const int gpx = p*16 + w*2 + sub;
            uint2 r00 = *(const uint2*)(xtb + (size_t)i00*64 + ch);
            uint2 r01 = *(const uint2*)(xtb + (size_t)i01*64 + ch);
            uint2 r10 = *(const uint2*)(xtb + (size_t)i10*64 + ch);
            uint2 r11 = *(const uint2*)(xtb + (size_t)i11*64 + ch);
            float4 v = make_float4(0.f,0.f,0.f,0.f);
            fma4(v, w00, h4_to_f4(r00));
            fma4(v, w01, h4_to_f4(r01));
            fma4(v, w10, h4_to_f4(r10));
            fma4(v, w11, h4_to_f4(r11));
            *(uint2*)(sg + DF_VHI + gpx*RSTRIDE + ch*2) =
                make_uint2(pack2h(v.x, v.y), pack2h(v.z, v.w));
        }
    };

    load_omb(0);
    comp_setup(0);
    load_omb(1);
    gather(0, 0);

    for (int s = 0; s < 9; ++s){
        __syncthreads();
        if (s < 8){
            comp_setup(s + 1);
            if (s < 7) load_omb(s + 2);
            gather(s + 1, (s + 1) & 1);
        }
        mma_tap<8>(sb + (s & 1)*DF_STG, DF_VHI, DF_WHI, lane, w*16, d);
    }

    const int g  = lane >> 2, t4 = lane & 3;
    float* dstb = out + (size_t)b*64*HW + row*128;
    #pragma unroll
    for (int nc = 0; nc < 8; ++nc){
        int oc0 = 8*nc + 2*t4;
        #pragma unroll
        for (int q = 0; q < 2; ++q){
            int oc = oc0 + q;
            float bv = b_dc[oc];
            dstb[(size_t)oc*HW + w*16 + g]     = d[nc][q]     + bv;
            dstb[(size_t)oc*HW + w*16 + g + 8] = d[nc][q + 2] + bv;
        }
    }
}

// ---------------- launch ----------------
extern "C" void kernel_launch(void* const* d_in, const int* in_sizes, int n_in,
                              void* d_out, int out_size){
    const float* x    = (const float*)d_in[0];
    const float* w_om = (const float*)d_in[1];
    const float* b_om = (const float*)d_in[2];
    const float* w_dc = (const float*)d_in[3];
    const float* b_dc = (const float*)d_in[4];
    float* out = (float*)d_out;

    cudaFuncSetAttribute(conv_om_kernel, cudaFuncAttributeMaxDynamicSharedMemorySize, CV_SMEM);
    cudaFuncSetAttribute(deform_kernel,  cudaFuncAttributeMaxDynamicSharedMemorySize, DF_SMEM);

    prep_kernel<<<216, 256>>>(w_om, w_dc);
    transpose_kernel<<<dim3(256, 8), 256>>>(x);
    conv_om_kernel<<<dim3(128, 8), 256, CV_SMEM>>>(b_om);
    deform_kernel <<<dim3(128, 8), 256, DF_SMEM>>>(b_dc, out);
}

// round 16
// speedup vs baseline: 1.9763x; 1.0637x over previous
#include <cuda_runtime.h>
#include <cuda_fp16.h>
#include <cstdint>

#define HW (128*128)

// ---------------- scratch (no allocations allowed) ----------------
__device__ float  g_om[8*27*HW];          // conv1 out: offsets raw, mask = 2*sigmoid
__device__ __half g_xt[8*HW*64];          // x transposed to NHWC f16 [b][pix][c]
__device__ __half g_wdc_h[9*4096];        // [kf][oc(64)][c(64)]  (f16)
__device__ __half g_wom_h[9*2048];        // [kf][oc(32, 27 used)][c(64)]  (f16)

// ---------------- helpers ----------------
__device__ __forceinline__ uint32_t smem_u32(const void* p){
    uint32_t a;
    asm("{ .reg .u64 t; cvta.to.shared.u64 t, %1; cvt.u32.u64 %0, t; }" : "=r"(a) : "l"(p));
    return a;
}
__device__ __forceinline__ void ldsm_x4(uint32_t &r0,uint32_t &r1,uint32_t &r2,uint32_t &r3, uint32_t addr){
    asm volatile("ldmatrix.sync.aligned.m8n8.x4.shared.b16 {%0,%1,%2,%3}, [%4];"
        : "=r"(r0),"=r"(r1),"=r"(r2),"=r"(r3) : "r"(addr));
}
__device__ __forceinline__ void mma16816(float* d, const uint32_t* a, const uint32_t* b){
    asm volatile("mma.sync.aligned.m16n8k16.row.col.f32.f16.f16.f32 "
        "{%0,%1,%2,%3}, {%4,%5,%6,%7}, {%8,%9}, {%0,%1,%2,%3};"
        : "+f"(d[0]),"+f"(d[1]),"+f"(d[2]),"+f"(d[3])
        : "r"(a[0]),"r"(a[1]),"r"(a[2]),"r"(a[3]), "r"(b[0]),"r"(b[1]));
}
__device__ __forceinline__ uint32_t pack2h(float a, float b){
    __half2 h2 = __floats2half2_rn(a, b);
    return *(uint32_t*)&h2;
}

__constant__ int cKY[9] = {-1,-1,-1, 0,0,0, 1,1,1};
__constant__ int cKX[9] = {-1, 0, 1,-1,0,1,-1,0,1};

// ---------------- kernel 0: weight fp32 -> f16 ----------------
__global__ void prep_kernel(const float* __restrict__ w_om, const float* __restrict__ w_dc){
    int i = blockIdx.x * blockDim.x + threadIdx.x;
    if (i < 9*4096){
        int kf = i >> 12, rem = i & 4095;
        int oc = rem >> 6, c = rem & 63;
        g_wdc_h[i] = __float2half_rn(w_dc[(oc*64 + c)*9 + kf]);
    }
    int j = i - 9*4096;
    if (j >= 0 && j < 9*2048){
        int kf = j >> 11, rem = j & 2047;
        int oc = rem >> 6, c = rem & 63;
        float w = (oc < 27) ? w_om[(oc*64 + c)*9 + kf] : 0.f;
        g_wom_h[j] = __float2half_rn(w);
    }
}

// ---------------- kernel 0b: NCHW fp32 -> NHWC f16 transpose ----------------
__global__ void __launch_bounds__(256)
transpose_kernel(const float* __restrict__ x){
    __shared__ float tile[64][65];
    const int b   = blockIdx.y;
    const int px0 = blockIdx.x * 64;
    const int t   = threadIdx.x;
    const float* xb = x + (size_t)b*64*HW + px0;
    {
        int cr = t >> 4, pq = t & 15;
        #pragma unroll
        for (int i = 0; i < 4; ++i){
            int c = i*16 + cr;
            float4 v = *(const float4*)(xb + (size_t)c*HW + pq*4);
            tile[c][pq*4+0]=v.x; tile[c][pq*4+1]=v.y;
            tile[c][pq*4+2]=v.z; tile[c][pq*4+3]=v.w;
        }
    }
    __syncthreads();
    {
        int px = t >> 2, cq = t & 3;
        __half* ob = g_xt + ((size_t)b*HW + px0 + px)*64 + cq*16;
        #pragma unroll
        for (int i = 0; i < 2; ++i){
            int c = cq*16 + i*8;
            uint4 u;
            u.x = pack2h(tile[c+0][px], tile[c+1][px]);
            u.y = pack2h(tile[c+2][px], tile[c+3][px]);
            u.z = pack2h(tile[c+4][px], tile[c+5][px]);
            u.w = pack2h(tile[c+6][px], tile[c+7][px]);
            ((uint4*)ob)[i] = u;
        }
    }
}

// =====================================================================
// smem geometry: rows padded to 72 halves (144 B), conflict-free ldmatrix
// =====================================================================
#define RSTRIDE 144

#define CV_XHI  0
#define CV_WHI  18432
#define CV_STG  23040
#define CV_SMEM (2*CV_STG)

#define DF_VHI  0
#define DF_WHI  18432
#define DF_STG  27648
#define DF_SMEM (2*DF_STG)

// A = values[128px][64c] f16, B = W[n][64c] f16 (plain f16 MMA)
template<int NC>
__device__ __forceinline__ void mma_tap(uint32_t stg, int vhi_off, int whi_off,
                                        int lane, int px0, float d[NC][4]){
    const int arow = px0 + (lane & 15);
    const int akof = (lane >> 4) * 16;
    const uint32_t aBase = stg + vhi_off + arow*RSTRIDE + akof;
    uint32_t ah[4][4];
    #pragma unroll
    for (int kc = 0; kc < 4; ++kc)
        ldsm_x4(ah[kc][0],ah[kc][1],ah[kc][2],ah[kc][3], aBase + kc*32);
    const uint32_t rb = (lane & 7)*RSTRIDE + ((lane >> 3) & 3)*16;
    #pragma unroll
    for (int nc = 0; nc < NC; ++nc){
        uint32_t bh[4][2];
        const uint32_t bRow = nc*8*RSTRIDE + rb;
        ldsm_x4(bh[0][0],bh[0][1],bh[1][0],bh[1][1], stg + whi_off + bRow);
        ldsm_x4(bh[2][0],bh[2][1],bh[3][0],bh[3][1], stg + whi_off + bRow + 64);
        #pragma unroll
        for (int kc = 0; kc < 4; ++kc)
            mma16816(d[nc], ah[kc], bh[kc]);
    }
}

// =====================================================================
// kernel 1: 3x3 conv 64->27 (+2*sigmoid) via f16 mma.sync
// gather: f16 source, verbatim uint2 copy into smem
// =====================================================================
__global__ void __launch_bounds__(256, 2)
conv_om_kernel(const float* __restrict__ b_om){
    extern __shared__ char smem[];
    const uint32_t sb = smem_u32(smem);
    const int b   = blockIdx.y;
    const int row = blockIdx.x;
    const int t   = threadIdx.x;
    const int w   = t >> 5, lane = t & 31;
    const int sub = lane >> 4;
    const int ch  = (lane & 15) * 4;
    const __half* xtb = g_xt + (size_t)b*HW*64;

    float d[4][4];
    #pragma unroll
    for (int i = 0; i < 4; ++i)
        #pragma unroll
        for (int k = 0; k < 4; ++k) d[i][k] = 0.f;

    auto gather = [&](int kf, int buf){
        char* sg = smem + buf*CV_STG;
        {
            const __half* src = g_wom_h + kf*2048;
            int oc = t >> 3, seg = t & 7;
            ((uint4*)(sg + CV_WHI + oc*RSTRIDE + seg*16))[0] = ((const uint4*)src)[t];
        }
        const int yy = row + cKY[kf];
        const bool okY = (yy >= 0 && yy < 128);
        #pragma unroll
        for (int p = 0; p < 8; ++p){
            int gpx = p*16 + w*2 + sub;
            int xx = gpx + cKX[kf];
            bool ok = okY && (xx >= 0 && xx < 128);
            uint2 v = make_uint2(0u, 0u);
            if (ok) v = *(const uint2*)(xtb + (size_t)(yy*128 + xx)*64 + ch);
            *(uint2*)(sg + CV_XHI + gpx*RSTRIDE + ch*2) = v;
        }
    };

    gather(0, 0);
    for (int s = 0; s < 9; ++s){
        __syncthreads();
        if (s < 8) gather(s + 1, (s + 1) & 1);
        mma_tap<4>(sb + (s & 1)*CV_STG, CV_XHI, CV_WHI, lane, w*16, d);
    }

    const int g  = lane >> 2, t4 = lane & 3;
    float* dstb = g_om + (size_t)b*27*HW + row*128;
    #pragma unroll
    for (int nc = 0; nc < 4; ++nc){
        int oc0 = 8*nc + 2*t4;
        #pragma unroll
        for (int q = 0; q < 2; ++q){
            int oc = oc0 + q;
            if (oc >= 27) continue;
            float bv = b_om[oc];
            float v0 = d[nc][q]     + bv;
            float v1 = d[nc][q + 2] + bv;
            if (oc >= 18){
                v0 = 2.f/(1.f + __expf(-v0));
                v1 = 2.f/(1.f + __expf(-v1));
            }
            dstb[(size_t)oc*HW + w*16 + g]     = v0;
            dstb[(size_t)oc*HW + w*16 + g + 8] = v1;
        }
    }
}

// =====================================================================
// kernel 2: deformable conv 64->64 via f16 mma.sync
// half2 bilinear: owner lane packs f16 weight pairs; lanes HFMA2 corners
// =====================================================================
__global__ void __launch_bounds__(256, 2)
deform_kernel(const float* __restrict__ b_dc, float* __restrict__ out){
    extern __shared__ char smem[];
    const uint32_t sb = smem_u32(smem);
    const int b   = blockIdx.y;
    const int row = blockIdx.x;
    const int t   = threadIdx.x;
    const int w   = t >> 5, lane = t & 31;
    const int sub = lane >> 4;
    const int ch  = (lane & 15) * 4;
    const __half* xtb = g_xt + (size_t)b*HW*64;
    const float*  omb = g_om + (size_t)b*27*HW;

    const int sl    = lane & 15;
    const int sgpx  = (sl & 7)*16 + w*2 + (sl >> 3);
    const int sgpix = row*128 + sgpx;

    float d[8][4];
    #pragma unroll
    for (int i = 0; i < 8; ++i)
        #pragma unroll
        for (int k = 0; k < 4; ++k) d[i][k] = 0.f;

    uint32_t pw01, pw23;                 // my pixel's f16-packed bilinear weights
    int      si00, si01, si10, si11;     // my pixel's corner indices
    float poy, pox, pom;                 // pending omb (next tap)

    auto load_omb = [&](int kf){
        poy = omb[(size_t)(2*kf    )*HW + sgpix];
        pox = omb[(size_t)(2*kf + 1)*HW + sgpix];
        pom = omb[(size_t)(18 + kf )*HW + sgpix];
    };
    auto comp_setup = [&](int kf){
        float py  = (float)(row  + cKY[kf]) + poy;
        float pxf = (float)(sgpx + cKX[kf]) + pox;
        float y0f = floorf(py), x0f = floorf(pxf);
        float fy = py - y0f, fx = pxf - x0f;
        int y0 = (int)y0f, x0 = (int)x0f, y1 = y0 + 1, x1 = x0 + 1;
        float vy0 = (y0 >= 0 && y0 <= 127) ? 1.f : 0.f;
        float vy1 = (y1 >= 0 && y1 <= 127) ? 1.f : 0.f;
        float vx0 = (x0 >= 0 && x0 <= 127) ? 1.f : 0.f;
        float vx1 = (x1 >= 0 && x1 <= 127) ? 1.f : 0.f;
        float w00 = (1.f-fy)*(1.f-fx)*vy0*vx0*pom;
        float w01 = (1.f-fy)*fx      *vy0*vx1*pom;
        float w10 = fy*(1.f-fx)      *vy1*vx0*pom;
        float w11 = fy*fx            *vy1*vx1*pom;
        pw01 = pack2h(w00, w01);
        pw23 = pack2h(w10, w11);
        int cy0 = min(max(y0,0),127), cy1 = min(max(y1,0),127);
        int cx0 = min(max(x0,0),127), cx1 = min(max(x1,0),127);
        si00 = cy0*128 + cx0; si01 = cy0*128 + cx1;
        si10 = cy1*128 + cx0; si11 = cy1*128 + cx1;
    };
    auto gather = [&](int kf, int buf){
        char* sg = smem + buf*DF_STG;
        {
            const __half* src = g_wdc_h + kf*4096;
            #pragma unroll
            for (int p = 0; p < 2; ++p){
                int j = t + p*256;
                int oc = j >> 3, seg = j & 7;
                ((uint4*)(sg + DF_WHI + oc*RSTRIDE + seg*16))[0] = ((const uint4*)src)[j];
            }
        }
        #pragma unroll
        for (int p = 0; p < 8; ++p){
            const int src = sub*8 + p;
            uint32_t w01p = __shfl_sync(0xffffffffu, pw01, src);
            uint32_t w23p = __shfl_sync(0xffffffffu, pw23, src);
            int i00 = __shfl_sync(0xffffffffu, si00, src);
            int i01 = __shfl_sync(0xffffffffu, si01, src);
            int i10 = __shfl_sync(0xffffffffu, si10, src);
            int i11 = __shfl_sync(0xffffffffu, si11, src);
            __half2 hw01 = *(__half2*)&w01p;
            __half2 hw23 = *(__half2*)&w23p;
            __half2 w00h = __low2half2(hw01),  w01h = __high2half2(hw01);
            __half2 w10h = __low2half2(hw23),  w11h = __high2half2(hw23);
            const int gpx = p*16 + w*2 + sub;
            uint2 r00 = *(const uint2*)(xtb + (size_t)i00*64 + ch);
            uint2 r01 = *(const uint2*)(xtb + (size_t)i01*64 + ch);
            uint2 r10 = *(const uint2*)(xtb + (size_t)i10*64 + ch);
            uint2 r11 = *(const uint2*)(xtb + (size_t)i11*64 + ch);
            __half2 v0 = __hmul2(w00h, *(__half2*)&r00.x);
            v0 = __hfma2(w01h, *(__half2*)&r01.x, v0);
            v0 = __hfma2(w10h, *(__half2*)&r10.x, v0);
            v0 = __hfma2(w11h, *(__half2*)&r11.x, v0);
            __half2 v1 = __hmul2(w00h, *(__half2*)&r00.y);
            v1 = __hfma2(w01h, *(__half2*)&r01.y, v1);
            v1 = __hfma2(w10h, *(__half2*)&r10.y, v1);
            v1 = __hfma2(w11h, *(__half2*)&r11.y, v1);
            *(uint2*)(sg + DF_VHI + gpx*RSTRIDE + ch*2) =
                make_uint2(*(uint32_t*)&v0, *(uint32_t*)&v1);
        }
    };

    load_omb(0);
    comp_setup(0);
    load_omb(1);
    gather(0, 0);

    for (int s = 0; s < 9; ++s){
        __syncthreads();
        if (s < 8){
            comp_setup(s + 1);
            if (s < 7) load_omb(s + 2);
            gather(s + 1, (s + 1) & 1);
        }
        mma_tap<8>(sb + (s & 1)*DF_STG, DF_VHI, DF_WHI, lane, w*16, d);
    }

    const int g  = lane >> 2, t4 = lane & 3;
    float* dstb = out + (size_t)b*64*HW + row*128;
    #pragma unroll
    for (int nc = 0; nc < 8; ++nc){
        int oc0 = 8*nc + 2*t4;
        #pragma unroll
        for (int q = 0; q < 2; ++q){
            int oc = oc0 + q;
            float bv = b_dc[oc];
            dstb[(size_t)oc*HW + w*16 + g]     = d[nc][q]     + bv;
            dstb[(size_t)oc*HW + w*16 + g + 8] = d[nc][q + 2] + bv;
        }
    }
}

// ---------------- launch ----------------
extern "C" void kernel_launch(void* const* d_in, const int* in_sizes, int n_in,
                              void* d_out, int out_size){
    const float* x    = (const float*)d_in[0];
    const float* w_om = (const float*)d_in[1];
    const float* b_om = (const float*)d_in[2];
    const float* w_dc = (const float*)d_in[3];
    const float* b_dc = (const float*)d_in[4];
    float* out = (float*)d_out;

    cudaFuncSetAttribute(conv_om_kernel, cudaFuncAttributeMaxDynamicSharedMemorySize, CV_SMEM);
    cudaFuncSetAttribute(deform_kernel,  cudaFuncAttributeMaxDynamicSharedMemorySize, DF_SMEM);

    prep_kernel<<<216, 256>>>(w_om, w_dc);
    transpose_kernel<<<dim3(256, 8), 256>>>(x);
    conv_om_kernel<<<dim3(128, 8), 256, CV_SMEM>>>(b_om);
    deform_kernel <<<dim3(128, 8), 256, DF_SMEM>>>(b_dc, out);
}

// round 17
// speedup vs baseline: 1.9859x; 1.0049x over previous
#include <cuda_runtime.h>
#include <cuda_fp16.h>
#include <cstdint>

#define HW (128*128)

// ---------------- scratch (no allocations allowed) ----------------
__device__ float  g_om[8*27*HW];          // conv1 out: offsets raw, mask = 2*sigmoid
__device__ __half g_xt[8*HW*64];          // x transposed to NHWC f16 [b][pix][c]
__device__ __half g_wdc_h[9*4096];        // [kf][oc(64)][c(64)]  (f16)
__device__ __half g_wom_h[9*2048];        // [kf][oc(32, 27 used)][c(64)]  (f16)

// ---------------- helpers ----------------
__device__ __forceinline__ uint32_t smem_u32(const void* p){
    uint32_t a;
    asm("{ .reg .u64 t; cvta.to.shared.u64 t, %1; cvt.u32.u64 %0, t; }" : "=r"(a) : "l"(p));
    return a;
}
__device__ __forceinline__ void ldsm_x4(uint32_t &r0,uint32_t &r1,uint32_t &r2,uint32_t &r3, uint32_t addr){
    asm volatile("ldmatrix.sync.aligned.m8n8.x4.shared.b16 {%0,%1,%2,%3}, [%4];"
        : "=r"(r0),"=r"(r1),"=r"(r2),"=r"(r3) : "r"(addr));
}
__device__ __forceinline__ void mma16816(float* d, const uint32_t* a, const uint32_t* b){
    asm volatile("mma.sync.aligned.m16n8k16.row.col.f32.f16.f16.f32 "
        "{%0,%1,%2,%3}, {%4,%5,%6,%7}, {%8,%9}, {%0,%1,%2,%3};"
        : "+f"(d[0]),"+f"(d[1]),"+f"(d[2]),"+f"(d[3])
        : "r"(a[0]),"r"(a[1]),"r"(a[2]),"r"(a[3]), "r"(b[0]),"r"(b[1]));
}
__device__ __forceinline__ uint32_t pack2h(float a, float b){
    __half2 h2 = __floats2half2_rn(a, b);
    return *(uint32_t*)&h2;
}

__constant__ int cKY[9] = {-1,-1,-1, 0,0,0, 1,1,1};
__constant__ int cKX[9] = {-1, 0, 1,-1,0,1,-1,0,1};

// ---------------- kernel 0: weight fp32 -> f16 ----------------
__global__ void prep_kernel(const float* __restrict__ w_om, const float* __restrict__ w_dc){
    int i = blockIdx.x * blockDim.x + threadIdx.x;
    if (i < 9*4096){
        int kf = i >> 12, rem = i & 4095;
        int oc = rem >> 6, c = rem & 63;
        g_wdc_h[i] = __float2half_rn(w_dc[(oc*64 + c)*9 + kf]);
    }
    int j = i - 9*4096;
    if (j >= 0 && j < 9*2048){
        int kf = j >> 11, rem = j & 2047;
        int oc = rem >> 6, c = rem & 63;
        float w = (oc < 27) ? w_om[(oc*64 + c)*9 + kf] : 0.f;
        g_wom_h[j] = __float2half_rn(w);
    }
}

// ---------------- kernel 0b: NCHW fp32 -> NHWC f16 transpose ----------------
__global__ void __launch_bounds__(256)
transpose_kernel(const float* __restrict__ x){
    __shared__ float tile[64][65];
    const int b   = blockIdx.y;
    const int px0 = blockIdx.x * 64;
    const int t   = threadIdx.x;
    const float* xb = x + (size_t)b*64*HW + px0;
    {
        int cr = t >> 4, pq = t & 15;
        #pragma unroll
        for (int i = 0; i < 4; ++i){
            int c = i*16 + cr;
            float4 v = *(const float4*)(xb + (size_t)c*HW + pq*4);
            tile[c][pq*4+0]=v.x; tile[c][pq*4+1]=v.y;
            tile[c][pq*4+2]=v.z; tile[c][pq*4+3]=v.w;
        }
    }
    __syncthreads();
    {
        int px = t >> 2, cq = t & 3;
        __half* ob = g_xt + ((size_t)b*HW + px0 + px)*64 + cq*16;
        #pragma unroll
        for (int i = 0; i < 2; ++i){
            int c = cq*16 + i*8;
            uint4 u;
            u.x = pack2h(tile[c+0][px], tile[c+1][px]);
            u.y = pack2h(tile[c+2][px], tile[c+3][px]);
            u.z = pack2h(tile[c+4][px], tile[c+5][px]);
            u.w = pack2h(tile[c+6][px], tile[c+7][px]);
            ((uint4*)ob)[i] = u;
        }
    }
}

// =====================================================================
// smem geometry: rows padded to 72 halves (144 B), conflict-free ldmatrix
// =====================================================================
#define RSTRIDE 144

#define CV_XHI  0
#define CV_WHI  18432
#define CV_STG  23040
#define CV_SMEM (2*CV_STG)

#define DF_VHI  0
#define DF_WHI  18432
#define DF_STG  27648
#define DF_SMEM (2*DF_STG)

// ---- conv GEMM core: warp = 16px x 32oc ----
__device__ __forceinline__ void mma_tap_cv(uint32_t stg, int lane, int px0, float d[4][4]){
    const int arow = px0 + (lane & 15);
    const int akof = (lane >> 4) * 16;
    const uint32_t aBase = stg + CV_XHI + arow*RSTRIDE + akof;
    uint32_t ah[4][4];
    #pragma unroll
    for (int kc = 0; kc < 4; ++kc)
        ldsm_x4(ah[kc][0],ah[kc][1],ah[kc][2],ah[kc][3], aBase + kc*32);
    const uint32_t rb = (lane & 7)*RSTRIDE + ((lane >> 3) & 3)*16;
    #pragma unroll
    for (int nc = 0; nc < 4; ++nc){
        uint32_t bh[4][2];
        const uint32_t bRow = nc*8*RSTRIDE + rb;
        ldsm_x4(bh[0][0],bh[0][1],bh[1][0],bh[1][1], stg + CV_WHI + bRow);
        ldsm_x4(bh[2][0],bh[2][1],bh[3][0],bh[3][1], stg + CV_WHI + bRow + 64);
        #pragma unroll
        for (int kc = 0; kc < 4; ++kc)
            mma16816(d[nc], ah[kc], bh[kc]);
    }
}

// ---- deform GEMM core: warp = 32px x 32oc, (4,2) tiling ----
// A fragments for both 16px row-tiles held in regs; B loaded per 8-oc chunk.
__device__ __forceinline__ void mma_tap_df(uint32_t stg, int lane, int pg, int og,
                                           float d[2][4][4]){
    const int akof = (lane >> 4) * 16;
    uint32_t ah[2][4][4];
    #pragma unroll
    for (int rbi = 0; rbi < 2; ++rbi){
        const uint32_t aBase = stg + DF_VHI
            + (pg*32 + rbi*16 + (lane & 15))*RSTRIDE + akof;
        #pragma unroll
        for (int kc = 0; kc < 4; ++kc)
            ldsm_x4(ah[rbi][kc][0],ah[rbi][kc][1],ah[rbi][kc][2],ah[rbi][kc][3],
                    aBase + kc*32);
    }
    const uint32_t rb = (lane & 7)*RSTRIDE + ((lane >> 3) & 3)*16;
    #pragma unroll
    for (int nc = 0; nc < 4; ++nc){
        uint32_t bh[4][2];
        const uint32_t bRow = (og*32 + nc*8)*RSTRIDE + rb;
        ldsm_x4(bh[0][0],bh[0][1],bh[1][0],bh[1][1], stg + DF_WHI + bRow);
        ldsm_x4(bh[2][0],bh[2][1],bh[3][0],bh[3][1], stg + DF_WHI + bRow + 64);
        #pragma unroll
        for (int rbi = 0; rbi < 2; ++rbi)
            #pragma unroll
            for (int kc = 0; kc < 4; ++kc)
                mma16816(d[rbi][nc], ah[rbi][kc], bh[kc]);
    }
}

// =====================================================================
// kernel 1: 3x3 conv 64->27 (+2*sigmoid) via f16 mma.sync, 3 CTA/SM
// =====================================================================
__global__ void __launch_bounds__(256, 3)
conv_om_kernel(const float* __restrict__ b_om){
    extern __shared__ char smem[];
    const uint32_t sb = smem_u32(smem);
    const int b   = blockIdx.y;
    const int row = blockIdx.x;
    const int t   = threadIdx.x;
    const int w   = t >> 5, lane = t & 31;
    const int sub = lane >> 4;
    const int ch  = (lane & 15) * 4;
    const __half* xtb = g_xt + (size_t)b*HW*64;

    float d[4][4];
    #pragma unroll
    for (int i = 0; i < 4; ++i)
        #pragma unroll
        for (int k = 0; k < 4; ++k) d[i][k] = 0.f;

    auto gather = [&](int kf, int buf){
        char* sg = smem + buf*CV_STG;
        {
            const __half* src = g_wom_h + kf*2048;
            int oc = t >> 3, seg = t & 7;
            ((uint4*)(sg + CV_WHI + oc*RSTRIDE + seg*16))[0] = ((const uint4*)src)[t];
        }
        const int yy = row + cKY[kf];
        const bool okY = (yy >= 0 && yy < 128);
        #pragma unroll
        for (int p = 0; p < 8; ++p){
            int gpx = p*16 + w*2 + sub;
            int xx = gpx + cKX[kf];
            bool ok = okY && (xx >= 0 && xx < 128);
            uint2 v = make_uint2(0u, 0u);
            if (ok) v = *(const uint2*)(xtb + (size_t)(yy*128 + xx)*64 + ch);
            *(uint2*)(sg + CV_XHI + gpx*RSTRIDE + ch*2) = v;
        }
    };

    gather(0, 0);
    for (int s = 0; s < 9; ++s){
        __syncthreads();
        if (s < 8) gather(s + 1, (s + 1) & 1);
        mma_tap_cv(sb + (s & 1)*CV_STG, lane, w*16, d);
    }

    const int g  = lane >> 2, t4 = lane & 3;
    float* dstb = g_om + (size_t)b*27*HW + row*128;
    #pragma unroll
    for (int nc = 0; nc < 4; ++nc){
        int oc0 = 8*nc + 2*t4;
        #pragma unroll
        for (int q = 0; q < 2; ++q){
            int oc = oc0 + q;
            if (oc >= 27) continue;
            float bv = b_om[oc];
            float v0 = d[nc][q]     + bv;
            float v1 = d[nc][q + 2] + bv;
            if (oc >= 18){
                v0 = 2.f/(1.f + __expf(-v0));
                v1 = 2.f/(1.f + __expf(-v1));
            }
            dstb[(size_t)oc*HW + w*16 + g]     = v0;
            dstb[(size_t)oc*HW + w*16 + g + 8] = v1;
        }
    }
}

// =====================================================================
// kernel 2: deformable conv 64->64 via f16 mma.sync, (4,2) tiling, 3 CTA/SM
// half2 bilinear gather (R16), offsets pipelined 2 taps ahead
// =====================================================================
__global__ void __launch_bounds__(256, 3)
deform_kernel(const float* __restrict__ b_dc, float* __restrict__ out){
    extern __shared__ char smem[];
    const uint32_t sb = smem_u32(smem);
    const int b   = blockIdx.y;
    const int row = blockIdx.x;
    const int t   = threadIdx.x;
    const int w   = t >> 5, lane = t & 31;
    const int pg  = w & 3, og = w >> 2;
    const int sub = lane >> 4;
    const int ch  = (lane & 15) * 4;
    const __half* xtb = g_xt + (size_t)b*HW*64;
    const float*  omb = g_om + (size_t)b*27*HW;

    const int sl    = lane & 15;
    const int sgpx  = (sl & 7)*16 + w*2 + (sl >> 3);
    const int sgpix = row*128 + sgpx;

    float d[2][4][4];
    #pragma unroll
    for (int i = 0; i < 2; ++i)
        #pragma unroll
        for (int j = 0; j < 4; ++j)
            #pragma unroll
            for (int k = 0; k < 4; ++k) d[i][j][k] = 0.f;

    uint32_t pw01, pw23;                 // my pixel's f16-packed bilinear weights
    int      si00, si01, si10, si11;     // my pixel's corner indices
    float poy, pox, pom;                 // pending omb (next tap)

    auto load_omb = [&](int kf){
        poy = omb[(size_t)(2*kf    )*HW + sgpix];
        pox = omb[(size_t)(2*kf + 1)*HW + sgpix];
        pom = omb[(size_t)(18 + kf )*HW + sgpix];
    };
    auto comp_setup = [&](int kf){
        float py  = (float)(row  + cKY[kf]) + poy;
        float pxf = (float)(sgpx + cKX[kf]) + pox;
        float y0f = floorf(py), x0f = floorf(pxf);
        float fy = py - y0f, fx = pxf - x0f;
        int y0 = (int)y0f, x0 = (int)x0f, y1 = y0 + 1, x1 = x0 + 1;
        float vy0 = (y0 >= 0 && y0 <= 127) ? 1.f : 0.f;
        float vy1 = (y1 >= 0 && y1 <= 127) ? 1.f : 0.f;
        float vx0 = (x0 >= 0 && x0 <= 127) ? 1.f : 0.f;
        float vx1 = (x1 >= 0 && x1 <= 127) ? 1.f : 0.f;
        float w00 = (1.f-fy)*(1.f-fx)*vy0*vx0*pom;
        float w01 = (1.f-fy)*fx      *vy0*vx1*pom;
        float w10 = fy*(1.f-fx)      *vy1*vx0*pom;
        float w11 = fy*fx            *vy1*vx1*pom;
        pw01 = pack2h(w00, w01);
        pw23 = pack2h(w10, w11);
        int cy0 = min(max(y0,0),127), cy1 = min(max(y1,0),127);
        int cx0 = min(max(x0,0),127), cx1 = min(max(x1,0),127);
        si00 = cy0*128 + cx0; si01 = cy0*128 + cx1;
        si10 = cy1*128 + cx0; si11 = cy1*128 + cx1;
    };
    auto gather = [&](int kf, int buf){
        char* sg = smem + buf*DF_STG;
        {
            const __half* src = g_wdc_h + kf*4096;
            #pragma unroll
            for (int p = 0; p < 2; ++p){
                int j = t + p*256;
                int oc = j >> 3, seg = j & 7;
                ((uint4*)(sg + DF_WHI + oc*RSTRIDE + seg*16))[0] = ((const uint4*)src)[j];
            }
        }
        #pragma unroll
        for (int p = 0; p < 8; ++p){
            const int src = sub*8 + p;
            uint32_t w01p = __shfl_sync(0xffffffffu, pw01, src);
            uint32_t w23p = __shfl_sync(0xffffffffu, pw23, src);
            int i00 = __shfl_sync(0xffffffffu, si00, src);
            int i01 = __shfl_sync(0xffffffffu, si01, src);
            int i10 = __shfl_sync(0xffffffffu, si10, src);
            int i11 = __shfl_sync(0xffffffffu, si11, src);
            __half2 hw01 = *(__half2*)&w01p;
            __half2 hw23 = *(__half2*)&w23p;
            __half2 w00h = __low2half2(hw01),  w01h = __high2half2(hw01);
            __half2 w10h = __low2half2(hw23),  w11h = __high2half2(hw23);
            const int gpx = p*16 + w*2 + sub;
            uint2 r00 = *(const uint2*)(xtb + (size_t)i00*64 + ch);
            uint2 r01 = *(const uint2*)(xtb + (size_t)i01*64 + ch);
            uint2 r10 = *(const uint2*)(xtb + (size_t)i10*64 + ch);
            uint2 r11 = *(const uint2*)(xtb + (size_t)i11*64 + ch);
            __half2 v0 = __hmul2(w00h, *(__half2*)&r00.x);
            v0 = __hfma2(w01h, *(__half2*)&r01.x, v0);
            v0 = __hfma2(w10h, *(__half2*)&r10.x, v0);
            v0 = __hfma2(w11h, *(__half2*)&r11.x, v0);
            __half2 v1 = __hmul2(w00h, *(__half2*)&r00.y);
            v1 = __hfma2(w01h, *(__half2*)&r01.y, v1);
            v1 = __hfma2(w10h, *(__half2*)&r10.y, v1);
            v1 = __hfma2(w11h, *(__half2*)&r11.y, v1);
            *(uint2*)(sg + DF_VHI + gpx*RSTRIDE + ch*2) =
                make_uint2(*(uint32_t*)&v0, *(uint32_t*)&v1);
        }
    };

    load_omb(0);
    comp_setup(0);
    load_omb(1);
    gather(0, 0);

    for (int s = 0; s < 9; ++s){
        __syncthreads();
        if (s < 8){
            comp_setup(s + 1);
            if (s < 7) load_omb(s + 2);
            gather(s + 1, (s + 1) & 1);
        }
        mma_tap_df(sb + (s & 1)*DF_STG, lane, pg, og, d);
    }

    const int g  = lane >> 2, t4 = lane & 3;
    float* dstb = out + (size_t)b*64*HW + row*128;
    #pragma unroll
    for (int rbi = 0; rbi < 2; ++rbi){
        #pragma unroll
        for (int nc = 0; nc < 4; ++nc){
            #pragma unroll
            for (int q = 0; q < 2; ++q){
                int oc = og*32 + nc*8 + 2*t4 + q;
                float bv = b_dc[oc];
                int px = pg*32 + rbi*16 + g;
                dstb[(size_t)oc*HW + px]     = d[rbi][nc][q]     + bv;
                dstb[(size_t)oc*HW + px + 8] = d[rbi][nc][q + 2] + bv;
            }
        }
    }
}

// ---------------- launch ----------------
extern "C" void kernel_launch(void* const* d_in, const int* in_sizes, int n_in,
                              void* d_out, int out_size){
    const float* x    = (const float*)d_in[0];
    const float* w_om = (const float*)d_in[1];
    const float* b_om = (const float*)d_in[2];
    const float* w_dc = (const float*)d_in[3];
    const float* b_dc = (const float*)d_in[4];
    float* out = (float*)d_out;

    cudaFuncSetAttribute(conv_om_kernel, cudaFuncAttributeMaxDynamicSharedMemorySize, CV_SMEM);
    cudaFuncSetAttribute(deform_kernel,  cudaFuncAttributeMaxDynamicSharedMemorySize, DF_SMEM);

    prep_kernel<<<216, 256>>>(w_om, w_dc);
    transpose_kernel<<<dim3(256, 8), 256>>>(x);
    conv_om_kernel<<<dim3(128, 8), 256, CV_SMEM>>>(b_om);
    deform_kernel <<<dim3(128, 8), 256, DF_SMEM>>>(b_dc, out);
}